// round 14
// baseline (speedup 1.0000x reference)
#include <cuda_runtime.h>
#include <math.h>
#include <stdint.h>

#define NN 50000
#define EE 500000
#define FF 128
#define HH 128
#define OUTD 768

// ---------------- scratch (device globals: no allocation allowed) ----------------
__device__ float g_Q  [(size_t)NN * HH];
__device__ float g_nK [(size_t)NN * HH];
__device__ float g_nV [(size_t)NN * HH];
__device__ float g_ex [(size_t)EE * HH];    // per-edge exp(Q[dst]*eK)
__device__ float g_ehR[(size_t)EE * HH];    // edge_h, k-permuted + tf32-rounded
__device__ float g_kR [(size_t)NN * FF];    // kind,   k-permuted + tf32-rounded
__device__ float g_den[(size_t)NN * HH];
__device__ float g_acc[(size_t)NN * HH];
__device__ float g_hn [(size_t)NN * HH];    // permuted+rounded at producer
__device__ float g_h  [(size_t)NN * HH];    // permuted+rounded at producer
__device__ float g_lin[(size_t)NN * OUTD];
__device__ float g_Snum[OUTD];
__device__ float g_S[1];
__device__ float g_Bt[540672];   // packed transposed weights (tf32, k-permuted)

// ---------------- helpers ----------------
__device__ __forceinline__ uint32_t smem_u32(const void* p) {
    uint32_t a;
    asm("{ .reg .u64 t; cvta.to.shared.u64 t, %1; cvt.u32.u64 %0, t; }" : "=r"(a) : "l"(p));
    return a;
}
__device__ __forceinline__ uint32_t f2tf32(float x) {
    uint32_t u;
    asm("cvt.rna.tf32.f32 %0, %1;" : "=r"(u) : "f"(x));
    return u;
}
__device__ __forceinline__ float rnd(float x) { return __uint_as_float(f2tf32(x)); }
__device__ __forceinline__ void mma1688(float* c, const uint32_t* a,
                                        uint32_t b0, uint32_t b1) {
    asm volatile(
        "mma.sync.aligned.m16n8k8.row.col.f32.tf32.tf32.f32 "
        "{%0,%1,%2,%3}, {%4,%5,%6,%7}, {%8,%9}, {%0,%1,%2,%3};"
        : "+f"(c[0]), "+f"(c[1]), "+f"(c[2]), "+f"(c[3])
        : "r"(a[0]), "r"(a[1]), "r"(a[2]), "r"(a[3]), "r"(b0), "r"(b1));
}
__device__ __forceinline__ void cp16(uint32_t dst, const void* src, int szn) {
    asm volatile("cp.async.ca.shared.global [%0], [%1], 16, %2;"
                 :: "r"(dst), "l"(src), "r"(szn) : "memory");
}
__device__ __forceinline__ void cpa_commit() {
    asm volatile("cp.async.commit_group;" ::: "memory");
}
template <int N> __device__ __forceinline__ void cpa_wait() {
    asm volatile("cp.async.wait_group %0;" :: "n"(N) : "memory");
}

#define PADK 20                       // floats per smem row (80B, 16-aligned)

// k-permutation within each 8-block: position 2t holds k=t, 2t+1 holds k=t+4
__device__ __forceinline__ int kperm(int k) {
    return (k & ~7) + ((k & 4) ? ((k & 3) * 2 + 1) : ((k & 3) * 2));
}

// ================= tf32 mma GEMM (512 thr, 32x32 warp tiles) ===================
// C = concat_k(A0,A1,A2) @ Bt^T. A segments PRE-ROUNDED + k-PERMUTED tf32;
// Bt [Ntot, ldb] K-major PRE-ROUNDED + k-PERMUTED tf32.
// mode 0: C = gemm + bias. If C1 set: blockIdx.x picks C/C1/C2 (+bias1/2), [M,128].
// mode 1: v = gemm + nK[src]; ex = exp(Q[dst]*v); C = ex; den[dst] += ex
// mode 2: v = gemm + nV[src]; acc[dst] += ex[row]*v (no C write)
struct TG {
    const float* A0; const float* A1; const float* A2;
    int k0, k1, k2;
    int bc0, bc1, bc2;
    int ldb;
    const float* Bt;
    const float* bias;
    const int* gidx; const float* gsrc;
    float* C; int M, Ntot;
    int mode;
    const int* dst; const float* Qm; float* den; float* acc; const float* ex;
    float* C1; float* C2; const float* bias1; const float* bias2;
};

#define BUF_U32 2560                  // 128*20 per stage per matrix
#define GSMEM_BYTES (6 * BUF_U32 * 4) // 61440; exchange pass needs 64*132*4=33792

__global__ __launch_bounds__(512, 2) void mma_gemm(TG p) {
    extern __shared__ uint32_t sh[];
    const uint32_t sbase = smem_u32(sh);

    const int tid = threadIdx.x;
    const int lid = tid & 31, wid = tid >> 5;       // 16 warps
    const int warp_m = wid & 3, warp_n = wid >> 2;  // 4 x 4, 32x32 per warp
    const int gID = lid >> 2, tig = lid & 3;
    const int m0 = blockIdx.y * 128, n0 = blockIdx.x * 128;

    float c[2][4][4];
#pragma unroll
    for (int mt = 0; mt < 2; mt++)
#pragma unroll
        for (int nt = 0; nt < 4; nt++)
#pragma unroll
            for (int i = 0; i < 4; i++) c[mt][nt][i] = 0.f;

    const int K = p.k0 + p.k1 + p.k2;
    const int nch = K >> 4;

    auto load_chunk = [&](int kb) {
        int off = kb << 4;
        const float* A; int lda; int bc;
        if (off < p.k0)             { A = p.A0; lda = p.k0; bc = p.bc0; }
        else if (off < p.k0 + p.k1) { A = p.A1; lda = p.k1; bc = p.bc1; off -= p.k0; }
        else                        { A = p.A2; lda = p.k2; bc = p.bc2; off -= p.k0 + p.k1; }
        int st = kb % 3;
        uint32_t ab = sbase + st * (BUF_U32 * 4);
        uint32_t bb = sbase + (3 + st) * (BUF_U32 * 4);
        int row = tid >> 2, kq = tid & 3;
        int gm = m0 + row;
        int gmc = gm < p.M ? gm : p.M - 1;
        cp16(ab + row * 80 + kq * 16,
             A + (size_t)gmc * lda + off + kq * 4, gm < p.M ? 16 : 0);
        cp16(bb + row * 80 + kq * 16,
             p.Bt + (size_t)(n0 + row) * p.ldb + bc + off + kq * 4, 16);
        cpa_commit();
    };

    load_chunk(0);
    load_chunk(1);

    for (int kb = 0; kb < nch; kb++) {
        if (kb + 2 < nch) load_chunk(kb + 2);
        int np = nch - kb - 1; if (np > 2) np = 2;
        if (np == 2) cpa_wait<2>();
        else if (np == 1) cpa_wait<1>();
        else cpa_wait<0>();
        __syncthreads();

        int st = kb % 3;
        const uint32_t* shA = sh + st * BUF_U32;
        const uint32_t* shB = sh + (3 + st) * BUF_U32;
#pragma unroll
        for (int k8 = 0; k8 < 16; k8 += 8) {
            // permuted layout: (k, k+4) adjacent -> 64-bit fragment loads, no cvt
            uint32_t a[2][4];
#pragma unroll
            for (int mt = 0; mt < 2; mt++) {
                int rb = (warp_m * 32 + mt * 16 + gID) * PADK + k8 + 2 * tig;
                uint2 lo = *(const uint2*)&shA[rb];
                uint2 hi = *(const uint2*)&shA[rb + 8 * PADK];
                a[mt][0] = lo.x; a[mt][2] = lo.y;
                a[mt][1] = hi.x; a[mt][3] = hi.y;
            }
#pragma unroll
            for (int nt = 0; nt < 4; nt++) {
                int nb = (warp_n * 32 + nt * 8 + gID) * PADK + k8 + 2 * tig;
                uint2 b = *(const uint2*)&shB[nb];
#pragma unroll
                for (int mt = 0; mt < 2; mt++)
                    mma1688(c[mt][nt], a[mt], b.x, b.y);
            }
        }
        __syncthreads();
    }

    // ---- exchange epilogue: smem round-trip -> row-major coalesced handling ----
    float* exs = (float*)sh;
    float* Cb = p.C; const float* bb = p.bias; int stride = p.Ntot; int cb = n0;
    if (p.mode == 0 && p.C1) {
        Cb = (blockIdx.x == 0) ? p.C : (blockIdx.x == 1 ? p.C1 : p.C2);
        bb = (blockIdx.x == 0) ? p.bias : (blockIdx.x == 1 ? p.bias1 : p.bias2);
        stride = HH; cb = 0;
    }

#pragma unroll
    for (int h = 0; h < 2; h++) {
        __syncthreads();
        if ((warp_m >> 1) == h) {
            int rbase = (warp_m & 1) * 32;
#pragma unroll
            for (int mt = 0; mt < 2; mt++)
#pragma unroll
            for (int hf = 0; hf < 2; hf++) {
                int rl = rbase + mt * 16 + hf * 8 + gID;
#pragma unroll
                for (int nt = 0; nt < 4; nt++) {
                    int ad = rl * 132 + warp_n * 32 + nt * 8 + tig * 2;
                    *(float2*)&exs[ad] =
                        make_float2(c[mt][nt][hf * 2], c[mt][nt][hf * 2 + 1]);
                }
            }
        }
        __syncthreads();
#pragma unroll
        for (int r = 0; r < 4; r++) {
            int rl = wid * 4 + r;
            int gm = m0 + h * 64 + rl;
            if (gm >= p.M) break;
            float4 v = *(float4*)&exs[rl * 132 + lid * 4];
            if (p.mode == 0) {
                int col = cb + lid * 4;
                if (bb) {
                    float4 b4 = *(const float4*)(bb + col);
                    v.x += b4.x; v.y += b4.y; v.z += b4.z; v.w += b4.w;
                }
                *(float4*)(Cb + (size_t)gm * stride + col) = v;
            } else if (p.mode == 1) {
                int sn = p.gidx[gm], d = p.dst[gm];
                float4 k4 = *(const float4*)(p.gsrc + (size_t)sn * HH + lid * 4);
                float4 q4 = *(const float4*)(p.Qm + (size_t)d * HH + lid * 4);
                float e0 = expf(q4.x * (v.x + k4.x));
                float e1 = expf(q4.y * (v.y + k4.y));
                float e2 = expf(q4.z * (v.z + k4.z));
                float e3 = expf(q4.w * (v.w + k4.w));
                *(float4*)(p.C + (size_t)gm * HH + lid * 4) =
                    make_float4(e0, e1, e2, e3);
                float* dr = p.den + (size_t)d * HH + lid * 4;
                atomicAdd(dr + 0, e0); atomicAdd(dr + 1, e1);
                atomicAdd(dr + 2, e2); atomicAdd(dr + 3, e3);
            } else {
                int sn = p.gidx[gm], d = p.dst[gm];
                float4 g4 = *(const float4*)(p.gsrc + (size_t)sn * HH + lid * 4);
                float4 e4 = *(const float4*)(p.ex + (size_t)gm * HH + lid * 4);
                float* ar = p.acc + (size_t)d * HH + lid * 4;
                atomicAdd(ar + 0, e4.x * (v.x + g4.x));
                atomicAdd(ar + 1, e4.y * (v.y + g4.y));
                atomicAdd(ar + 2, e4.z * (v.z + g4.z));
                atomicAdd(ar + 3, e4.w * (v.w + g4.w));
            }
        }
    }
}

// ---------------- pre-round + k-permute copy (GEMM-A sources) ----------------
// out 8-block = [k0,k4,k1,k5,k2,k6,k3,k7] of in, tf32-rounded.
__global__ __launch_bounds__(256) void permute_round_k(
    const float* __restrict__ in, float* __restrict__ out, int nblk)
{
    int i = blockIdx.x * 256 + threadIdx.x;
    if (i >= nblk) return;
    const float4* ip = (const float4*)(in + (size_t)i * 8);
    float4 v0 = ip[0], v1 = ip[1];
    float4 o0 = make_float4(rnd(v0.x), rnd(v1.x), rnd(v0.y), rnd(v1.y));
    float4 o1 = make_float4(rnd(v0.z), rnd(v1.z), rnd(v0.w), rnd(v1.w));
    float4* op = (float4*)(out + (size_t)i * 8);
    op[0] = o0; op[1] = o1;
}

// ---------------- fused weight transposes (tf32 pre-round + k-permute) ---------
struct TransDesc { const float* W; float* O; int srcN; int KB; int ldb; };
struct TransParams { TransDesc t[14]; int start[15]; };

__global__ void transpose_all_k(TransParams tp) {
    __shared__ float t[32][33];
    int b = blockIdx.x;
    int i = 0;
#pragma unroll
    for (int j = 0; j < 14; j++)
        if (b >= tp.start[j + 1]) i = j + 1;
    const TransDesc d = tp.t[i];
    int rem = b - tp.start[i];
    int ntk = d.KB >> 5;
    int tx = (rem % ntk) * 32;       // k tile
    int ty = (rem / ntk) * 32;       // n tile
#pragma unroll
    for (int r = 0; r < 4; r++) {
        int k = tx + threadIdx.y + r * 8, n = ty + threadIdx.x;
        t[threadIdx.y + r * 8][threadIdx.x] = d.W[(size_t)k * d.srcN + n];
    }
    __syncthreads();
#pragma unroll
    for (int r = 0; r < 4; r++) {
        int n = ty + threadIdx.y + r * 8, k = tx + threadIdx.x;
        d.O[(size_t)n * d.ldb + kperm(k)] =
            __uint_as_float(f2tf32(t[threadIdx.x][threadIdx.y + r * 8]));
    }
}

// ---------------- node div (permuted+rounded output: GEMM-A consumer) ----------
__global__ __launch_bounds__(256) void node_div_k(
    const float* __restrict__ den, const float* __restrict__ acc,
    float* __restrict__ out)
{
    int i = blockIdx.x * 256 + threadIdx.x;      // one 8-block per thread
    if (i >= NN * HH / 8) return;
    const float4* dp = (const float4*)(den + (size_t)i * 8);
    const float4* ap = (const float4*)(acc + (size_t)i * 8);
    float4 d0 = dp[0], d1 = dp[1], a0 = ap[0], a1 = ap[1];
    float v[8];
    v[0] = (d0.x > 0.f) ? a0.x / d0.x : 0.f;
    v[1] = (d0.y > 0.f) ? a0.y / d0.y : 0.f;
    v[2] = (d0.z > 0.f) ? a0.z / d0.z : 0.f;
    v[3] = (d0.w > 0.f) ? a0.w / d0.w : 0.f;
    v[4] = (d1.x > 0.f) ? a1.x / d1.x : 0.f;
    v[5] = (d1.y > 0.f) ? a1.y / d1.y : 0.f;
    v[6] = (d1.z > 0.f) ? a1.z / d1.z : 0.f;
    v[7] = (d1.w > 0.f) ? a1.w / d1.w : 0.f;
    float4* op = (float4*)(out + (size_t)i * 8);
    op[0] = make_float4(rnd(v[0]), rnd(v[4]), rnd(v[1]), rnd(v[5]));
    op[1] = make_float4(rnd(v[2]), rnd(v[6]), rnd(v[3]), rnd(v[7]));
}

// ---------------- layernorm 128 (permuted+rounded output: GEMM-A consumer) -----
__global__ __launch_bounds__(128) void ln128_k(
    const float* __restrict__ x, const float* __restrict__ g,
    const float* __restrict__ b, float* __restrict__ y)
{
    int row = blockIdx.x, t = threadIdx.x;
    float v = x[(size_t)row * 128 + t];
    float s = v, s2 = v * v;
#pragma unroll
    for (int o = 16; o > 0; o >>= 1) {
        s  += __shfl_xor_sync(0xffffffffu, s, o);
        s2 += __shfl_xor_sync(0xffffffffu, s2, o);
    }
    __shared__ float ws[4], ws2[4];
    int w = t >> 5, l = t & 31;
    if (l == 0) { ws[w] = s; ws2[w] = s2; }
    __syncthreads();
    s  = ws[0] + ws[1] + ws[2] + ws[3];
    s2 = ws2[0] + ws2[1] + ws2[2] + ws2[3];
    float mu  = s * (1.f / 128.f);
    float var = s2 * (1.f / 128.f) - mu * mu;
    float r = rsqrtf(var + 1e-5f);
    float hv = (v - mu) * r * g[t] + b[t];
    y[(size_t)row * 128 + kperm(t)] = __uint_as_float(f2tf32(hv));
}

// ---------------- fused LN768 + gate + pool ----------------
#define LGP_BLOCKS 400
__global__ __launch_bounds__(256) void ln_gate_pool_k(
    const float* __restrict__ lin, const float* __restrict__ g,
    const float* __restrict__ b, const float* __restrict__ gw,
    const float* __restrict__ gb, float* __restrict__ Snum,
    float* __restrict__ S)
{
    __shared__ float ps[8 * 768];
    int wid = threadIdx.x >> 5, lid = threadIdx.x & 31;
    int gwarp = blockIdx.x * 8 + wid;
    const int NW = LGP_BLOCKS * 8;

    float accv[24];
#pragma unroll
    for (int i = 0; i < 24; i++) accv[i] = 0.f;
    float eacc = 0.f;
    float gbv = gb[0];

    for (int row = gwarp; row < NN; row += NW) {
        const float* xr = lin + (size_t)row * 768;
        float x[24];
        float s = 0.f, s2 = 0.f;
#pragma unroll
        for (int k = 0; k < 6; k++) {
            float4 v = *(const float4*)(xr + k * 128 + lid * 4);
            x[k * 4 + 0] = v.x; x[k * 4 + 1] = v.y;
            x[k * 4 + 2] = v.z; x[k * 4 + 3] = v.w;
            s += v.x + v.y + v.z + v.w;
            s2 += v.x * v.x + v.y * v.y + v.z * v.z + v.w * v.w;
        }
#pragma unroll
        for (int o = 16; o > 0; o >>= 1) {
            s  += __shfl_xor_sync(0xffffffffu, s, o);
            s2 += __shfl_xor_sync(0xffffffffu, s2, o);
        }
        float mu  = s * (1.f / 768.f);
        float var = s2 * (1.f / 768.f) - mu * mu;
        float r = rsqrtf(var + 1e-5f);
        float dot = 0.f;
#pragma unroll
        for (int k = 0; k < 6; k++) {
            int col = k * 128 + lid * 4;
            float4 g4 = *(const float4*)(g + col);
            float4 b4 = *(const float4*)(b + col);
            float4 w4 = *(const float4*)(gw + col);
            float h0 = (x[k * 4 + 0] - mu) * r * g4.x + b4.x;
            float h1 = (x[k * 4 + 1] - mu) * r * g4.y + b4.y;
            float h2 = (x[k * 4 + 2] - mu) * r * g4.z + b4.z;
            float h3 = (x[k * 4 + 3] - mu) * r * g4.w + b4.w;
            x[k * 4 + 0] = h0; x[k * 4 + 1] = h1;
            x[k * 4 + 2] = h2; x[k * 4 + 3] = h3;
            dot = fmaf(h0, w4.x, dot); dot = fmaf(h1, w4.y, dot);
            dot = fmaf(h2, w4.z, dot); dot = fmaf(h3, w4.w, dot);
        }
#pragma unroll
        for (int o = 16; o > 0; o >>= 1)
            dot += __shfl_xor_sync(0xffffffffu, dot, o);
        float e = expf(dot + gbv);
        eacc += e;
#pragma unroll
        for (int i = 0; i < 24; i++) accv[i] = fmaf(e, x[i], accv[i]);
    }

#pragma unroll
    for (int k = 0; k < 6; k++) {
        int col = k * 128 + lid * 4;
        *(float4*)&ps[wid * 768 + col] = make_float4(
            accv[k * 4 + 0], accv[k * 4 + 1], accv[k * 4 + 2], accv[k * 4 + 3]);
    }
    __syncthreads();
    for (int cidx = threadIdx.x; cidx < 768; cidx += 256) {
        float sum = 0.f;
#pragma unroll
        for (int w = 0; w < 8; w++) sum += ps[w * 768 + cidx];
        atomicAdd(Snum + cidx, sum);
    }
    if (lid == 0) atomicAdd(S, eacc);
}

__global__ void pool_norm_k(const float* __restrict__ Snum,
                            const float* __restrict__ S,
                            float* __restrict__ out) {
    int c = blockIdx.x * 256 + threadIdx.x;
    if (c < OUTD) out[c] = Snum[c] / S[0];
}

// ---------------- host ----------------
static void launch_tg(const TG& p) {
    dim3 grid(p.Ntot / 128, (p.M + 127) / 128);
    mma_gemm<<<grid, 512, GSMEM_BYTES>>>(p);
}

extern "C" void kernel_launch(void* const* d_in, const int* in_sizes, int n_in,
                              void* d_out, int out_size) {
    const float* kind   = (const float*)d_in[0];
    const float* edge_h = (const float*)d_in[1];
    const int*   src    = (const int*)  d_in[2];
    const int*   dst    = (const int*)  d_in[3];
    const float* KW  = (const float*)d_in[4];  const float* Kb  = (const float*)d_in[5];
    const float* VW  = (const float*)d_in[6];  const float* Vb  = (const float*)d_in[7];
    const float* QW  = (const float*)d_in[8];  const float* Qb  = (const float*)d_in[9];
    const float* WW  = (const float*)d_in[10]; const float* Wb  = (const float*)d_in[11];
    const float* K2W = (const float*)d_in[12]; const float* K2b = (const float*)d_in[13];
    const float* V2W = (const float*)d_in[14]; const float* V2b = (const float*)d_in[15];
    const float* Q2W = (const float*)d_in[16]; const float* Q2b = (const float*)d_in[17];
    const float* W2W = (const float*)d_in[18]; const float* W2b = (const float*)d_in[19];
    const float* ln1g = (const float*)d_in[20]; const float* ln1b = (const float*)d_in[21];
    const float* ln2g = (const float*)d_in[22]; const float* ln2b = (const float*)d_in[23];
    const float* gw  = (const float*)d_in[24]; const float* gb  = (const float*)d_in[25];
    float* out = (float*)d_out;

    static float *pQ = nullptr, *pnK, *pnV, *pex, *pehR, *pkR, *pden, *pacc,
                 *phn, *ph, *plin, *pSnum, *pS, *pBt;
    if (!pQ) {
        cudaGetSymbolAddress((void**)&pQ,   g_Q);
        cudaGetSymbolAddress((void**)&pnK,  g_nK);
        cudaGetSymbolAddress((void**)&pnV,  g_nV);
        cudaGetSymbolAddress((void**)&pex,  g_ex);
        cudaGetSymbolAddress((void**)&pehR, g_ehR);
        cudaGetSymbolAddress((void**)&pkR,  g_kR);
        cudaGetSymbolAddress((void**)&pden, g_den);
        cudaGetSymbolAddress((void**)&pacc, g_acc);
        cudaGetSymbolAddress((void**)&phn,  g_hn);
        cudaGetSymbolAddress((void**)&ph,   g_h);
        cudaGetSymbolAddress((void**)&plin, g_lin);
        cudaGetSymbolAddress((void**)&pSnum, g_Snum);
        cudaGetSymbolAddress((void**)&pS,   g_S);
        cudaGetSymbolAddress((void**)&pBt,  g_Bt);
        cudaFuncSetAttribute(mma_gemm, cudaFuncAttributeMaxDynamicSharedMemorySize,
                             GSMEM_BYTES);
    }

    // packed transposed-weight offsets (floats)
    const int oN1  = 0;        // [384,128]: Q | nodeK | nodeV
    const int oKe1 = 49152;    // [128,128]: KW edge part
    const int oVe1 = 65536;    // [128,128]: VW edge part
    const int oW1  = 81920;    // [128,256]: WW full
    const int oN2  = 114688;   // [384,256]: Q2 | K2 node | V2 node
    const int oKe2 = 212992;   // [128,128]: K2W edge part
    const int oVe2 = 229376;   // [128,128]: V2W edge part
    const int oW2  = 245760;   // [768,384]: W2W full

    TransParams tp;
    tp.t[0]  = {QW,                pBt + oN1,             128, 128, 128};
    tp.t[1]  = {KW,                pBt + oN1 + 128 * 128, 128, 128, 128};
    tp.t[2]  = {VW,                pBt + oN1 + 256 * 128, 128, 128, 128};
    tp.t[3]  = {KW + 128 * 128,    pBt + oKe1,            128, 128, 128};
    tp.t[4]  = {VW + 128 * 128,    pBt + oVe1,            128, 128, 128};
    tp.t[5]  = {WW,                pBt + oW1,             128, 256, 256};
    tp.t[6]  = {Q2W,               pBt + oN2,             128, 256, 256};
    tp.t[7]  = {K2W,               pBt + oN2 + 128 * 256,       128, 128, 256};
    tp.t[8]  = {K2W + 256 * 128,   pBt + oN2 + 128 * 256 + 128, 128, 128, 256};
    tp.t[9]  = {V2W,               pBt + oN2 + 256 * 256,       128, 128, 256};
    tp.t[10] = {V2W + 256 * 128,   pBt + oN2 + 256 * 256 + 128, 128, 128, 256};
    tp.t[11] = {K2W + 128 * 128,   pBt + oKe2,            128, 128, 128};
    tp.t[12] = {V2W + 128 * 128,   pBt + oVe2,            128, 128, 128};
    tp.t[13] = {W2W,               pBt + oW2,             768, 384, 384};
    int s = 0;
    for (int i = 0; i < 14; i++) {
        tp.start[i] = s;
        s += (tp.t[i].srcN >> 5) * (tp.t[i].KB >> 5);
    }
    tp.start[14] = s;
    transpose_all_k<<<s, dim3(32, 8)>>>(tp);

    // pre-round + permute GEMM-A sources
    permute_round_k<<<(NN * FF / 8 + 255) / 256, 256>>>(kind, pkR, NN * FF / 8);
    permute_round_k<<<(EE * HH / 8 + 255) / 256, 256>>>(edge_h, pehR, EE * HH / 8);

    const size_t nh_bytes = (size_t)NN * HH * sizeof(float);
    TG p;

    // ===================== layer 1 =====================
    cudaMemsetAsync(pden, 0, nh_bytes);
    cudaMemsetAsync(pacc, 0, nh_bytes);

    // fused node GEMM: Q | nodeK | nodeV = kind @ {QW, KW[0:F], VW[0:F]}
    p = {pkR, nullptr, nullptr, FF, 0, 0, 0, 0, 0, 128, pBt + oN1,
         Qb, nullptr, nullptr, pQ, NN, 384, 0,
         nullptr, nullptr, nullptr, nullptr, nullptr,
         pnK, pnV, Kb, Vb};
    launch_tg(p);
    // eK fused: ex = exp(Q[dst] * (edge_h@KWe + nodeK[src])); den[dst]+=ex
    p = {pehR, nullptr, nullptr, FF, 0, 0, 0, 0, 0, 128, pBt + oKe1,
         nullptr, src, pnK, pex, EE, HH, 1,
         dst, pQ, pden, nullptr, nullptr,
         nullptr, nullptr, nullptr, nullptr};
    launch_tg(p);
    // eV fused: acc[dst] += ex * (edge_h@VWe + nodeV[src])
    p = {pehR, nullptr, nullptr, FF, 0, 0, 0, 0, 0, 128, pBt + oVe1,
         nullptr, src, pnV, nullptr, EE, HH, 2,
         dst, nullptr, nullptr, pacc, pex,
         nullptr, nullptr, nullptr, nullptr};
    launch_tg(p);

    node_div_k<<<(NN * HH / 8 + 255) / 256, 256>>>(pden, pacc, phn);

    // lin1 = concat(h_n, kind) @ WW + Wb ; h = LN(lin1)
    p = {phn, pkR, nullptr, HH, FF, 0, 0, HH, 0, 256, pBt + oW1,
         Wb, nullptr, nullptr, plin, NN, HH, 0,
         nullptr, nullptr, nullptr, nullptr, nullptr,
         nullptr, nullptr, nullptr, nullptr};
    launch_tg(p);
    ln128_k<<<NN, 128>>>(plin, ln1g, ln1b, ph);

    // ===================== layer 2 =====================
    cudaMemsetAsync(pden, 0, nh_bytes);
    cudaMemsetAsync(pacc, 0, nh_bytes);

    // fused node GEMM: Q2 | nodeK2 | nodeV2 = [kind,h] @ packed
    p = {pkR, ph, nullptr, FF, HH, 0, 0, 128, 0, 256, pBt + oN2,
         Q2b, nullptr, nullptr, pQ, NN, 384, 0,
         nullptr, nullptr, nullptr, nullptr, nullptr,
         pnK, pnV, K2b, V2b};
    launch_tg(p);
    // eK2
    p = {pehR, nullptr, nullptr, FF, 0, 0, 0, 0, 0, 128, pBt + oKe2,
         nullptr, src, pnK, pex, EE, HH, 1,
         dst, pQ, pden, nullptr, nullptr,
         nullptr, nullptr, nullptr, nullptr};
    launch_tg(p);
    // eV2
    p = {pehR, nullptr, nullptr, FF, 0, 0, 0, 0, 0, 128, pBt + oVe2,
         nullptr, src, pnV, nullptr, EE, HH, 2,
         dst, nullptr, nullptr, pacc, pex,
         nullptr, nullptr, nullptr, nullptr};
    launch_tg(p);

    node_div_k<<<(NN * HH / 8 + 255) / 256, 256>>>(pden, pacc, phn);

    // lin2 = concat(h_n1, h, kind) @ W2W + W2b (LN fused below)
    p = {phn, ph, pkR, HH, HH, FF, 0, HH, 2 * HH, 384, pBt + oW2,
         W2b, nullptr, nullptr, plin, NN, OUTD, 0,
         nullptr, nullptr, nullptr, nullptr, nullptr,
         nullptr, nullptr, nullptr, nullptr};
    launch_tg(p);

    // ===================== fused LN + gate + pool =====================
    cudaMemsetAsync(pSnum, 0, OUTD * sizeof(float));
    cudaMemsetAsync(pS, 0, sizeof(float));
    ln_gate_pool_k<<<LGP_BLOCKS, 256>>>(plin, ln2g, ln2b, gw, gb, pSnum, pS);
    pool_norm_k<<<3, 256>>>(pSnum, pS, out);
}

// round 15
// speedup vs baseline: 1.1378x; 1.1378x over previous
#include <cuda_runtime.h>
#include <math.h>
#include <stdint.h>

#define NN 50000
#define EE 500000
#define FF 128
#define HH 128
#define OUTD 768

// ---------------- scratch (device globals: no allocation allowed) ----------------
__device__ float g_Q  [(size_t)NN * HH];
__device__ float g_nK [(size_t)NN * HH];
__device__ float g_nV [(size_t)NN * HH];
__device__ float g_ex [(size_t)EE * HH];    // per-edge exp(Q[dst]*eK)
__device__ float g_ehR[(size_t)EE * HH];    // edge_h, tf32-pre-rounded
__device__ float g_kR [(size_t)NN * FF];    // kind,   tf32-pre-rounded
__device__ float g_den[(size_t)NN * HH];
__device__ float g_acc[(size_t)NN * HH];
__device__ float g_hn [(size_t)NN * HH];    // tf32-pre-rounded at producer
__device__ float g_h  [(size_t)NN * HH];    // tf32-pre-rounded at producer
__device__ float g_lin[(size_t)NN * OUTD];
__device__ float g_Snum[OUTD];
__device__ float g_S[1];
__device__ float g_Bt[540672];   // packed transposed weights (tf32, k-permuted)

// ---------------- helpers ----------------
__device__ __forceinline__ uint32_t smem_u32(const void* p) {
    uint32_t a;
    asm("{ .reg .u64 t; cvta.to.shared.u64 t, %1; cvt.u32.u64 %0, t; }" : "=r"(a) : "l"(p));
    return a;
}
__device__ __forceinline__ uint32_t f2tf32(float x) {
    uint32_t u;
    asm("cvt.rna.tf32.f32 %0, %1;" : "=r"(u) : "f"(x));
    return u;
}
__device__ __forceinline__ float rnd(float x) { return __uint_as_float(f2tf32(x)); }
__device__ __forceinline__ void mma1688(float* c, const uint32_t* a,
                                        uint32_t b0, uint32_t b1) {
    asm volatile(
        "mma.sync.aligned.m16n8k8.row.col.f32.tf32.tf32.f32 "
        "{%0,%1,%2,%3}, {%4,%5,%6,%7}, {%8,%9}, {%0,%1,%2,%3};"
        : "+f"(c[0]), "+f"(c[1]), "+f"(c[2]), "+f"(c[3])
        : "r"(a[0]), "r"(a[1]), "r"(a[2]), "r"(a[3]), "r"(b0), "r"(b1));
}
__device__ __forceinline__ void cp16(uint32_t dst, const void* src, int szn) {
    asm volatile("cp.async.ca.shared.global [%0], [%1], 16, %2;"
                 :: "r"(dst), "l"(src), "r"(szn) : "memory");
}
__device__ __forceinline__ void cpa_commit() {
    asm volatile("cp.async.commit_group;" ::: "memory");
}
template <int N> __device__ __forceinline__ void cpa_wait() {
    asm volatile("cp.async.wait_group %0;" :: "n"(N) : "memory");
}

#define PADKA 20   // A smem stride (floats): conflict-free for scalar LDS
#define PADKB 24   // B smem stride (floats): conflict-free for LDS.64 (gID*12+tig)

// k-permutation within each 8-block (B ONLY): position 2t <- k=t, 2t+1 <- k=t+4
__device__ __forceinline__ int kperm(int k) {
    return (k & ~7) + ((k & 4) ? ((k & 3) * 2 + 1) : ((k & 3) * 2));
}

// ================= tf32 mma GEMM (512 thr, 32x32 warp tiles) ===================
// C = concat_k(A0,A1,A2) @ Bt^T. A segments PRE-ROUNDED tf32 (plain order);
// Bt [Ntot, ldb] K-major PRE-ROUNDED + k-PERMUTED tf32.
// mode 0: C = gemm + bias. If C1 set: blockIdx.x picks C/C1/C2 (+bias1/2), [M,128].
// mode 1: v = gemm + nK[src]; ex = exp(Q[dst]*v); C = ex; den[dst] += ex
// mode 2: v = gemm + nV[src]; acc[dst] += ex[row]*v (no C write)
struct TG {
    const float* A0; const float* A1; const float* A2;
    int k0, k1, k2;
    int bc0, bc1, bc2;
    int ldb;
    const float* Bt;
    const float* bias;
    const int* gidx; const float* gsrc;
    float* C; int M, Ntot;
    int mode;
    const int* dst; const float* Qm; float* den; float* acc; const float* ex;
    float* C1; float* C2; const float* bias1; const float* bias2;
};

#define A_ST 2560                     // 128*20 u32 per A stage
#define B_ST 3072                     // 128*24 u32 per B stage
#define GSMEM_BYTES ((3 * A_ST + 3 * B_ST) * 4)   // 67584; exchange needs 33792

__global__ __launch_bounds__(512, 2) void mma_gemm(TG p) {
    extern __shared__ uint32_t sh[];
    const uint32_t sbase = smem_u32(sh);

    const int tid = threadIdx.x;
    const int lid = tid & 31, wid = tid >> 5;       // 16 warps
    const int warp_m = wid & 3, warp_n = wid >> 2;  // 4 x 4, 32x32 per warp
    const int gID = lid >> 2, tig = lid & 3;
    const int m0 = blockIdx.y * 128, n0 = blockIdx.x * 128;

    float c[2][4][4];
#pragma unroll
    for (int mt = 0; mt < 2; mt++)
#pragma unroll
        for (int nt = 0; nt < 4; nt++)
#pragma unroll
            for (int i = 0; i < 4; i++) c[mt][nt][i] = 0.f;

    const int K = p.k0 + p.k1 + p.k2;
    const int nch = K >> 4;

    auto load_chunk = [&](int kb) {
        int off = kb << 4;
        const float* A; int lda; int bc;
        if (off < p.k0)             { A = p.A0; lda = p.k0; bc = p.bc0; }
        else if (off < p.k0 + p.k1) { A = p.A1; lda = p.k1; bc = p.bc1; off -= p.k0; }
        else                        { A = p.A2; lda = p.k2; bc = p.bc2; off -= p.k0 + p.k1; }
        int st = kb % 3;
        uint32_t ab = sbase + st * (A_ST * 4);
        uint32_t bb = sbase + (3 * A_ST + st * B_ST) * 4;
        int row = tid >> 2, kq = tid & 3;
        int gm = m0 + row;
        int gmc = gm < p.M ? gm : p.M - 1;
        cp16(ab + row * 80 + kq * 16,
             A + (size_t)gmc * lda + off + kq * 4, gm < p.M ? 16 : 0);
        cp16(bb + row * 96 + kq * 16,
             p.Bt + (size_t)(n0 + row) * p.ldb + bc + off + kq * 4, 16);
        cpa_commit();
    };

    load_chunk(0);
    load_chunk(1);

    for (int kb = 0; kb < nch; kb++) {
        if (kb + 2 < nch) load_chunk(kb + 2);
        int np = nch - kb - 1; if (np > 2) np = 2;
        if (np == 2) cpa_wait<2>();
        else if (np == 1) cpa_wait<1>();
        else cpa_wait<0>();
        __syncthreads();

        int st = kb % 3;
        const uint32_t* shA = sh + st * A_ST;
        const uint32_t* shB = sh + 3 * A_ST + st * B_ST;
#pragma unroll
        for (int k8 = 0; k8 < 16; k8 += 8) {
            uint32_t a[2][4];
#pragma unroll
            for (int mt = 0; mt < 2; mt++) {
                int rb = (warp_m * 32 + mt * 16 + gID) * PADKA + k8 + tig;
                a[mt][0] = shA[rb];
                a[mt][1] = shA[rb + 8 * PADKA];
                a[mt][2] = shA[rb + 4];
                a[mt][3] = shA[rb + 8 * PADKA + 4];
            }
#pragma unroll
            for (int nt = 0; nt < 4; nt++) {
                // B permuted: positions (2tig, 2tig+1) = logical k (tig, tig+4)
                int nb = (warp_n * 32 + nt * 8 + gID) * PADKB + k8 + 2 * tig;
                uint2 b = *(const uint2*)&shB[nb];
#pragma unroll
                for (int mt = 0; mt < 2; mt++)
                    mma1688(c[mt][nt], a[mt], b.x, b.y);
            }
        }
        __syncthreads();
    }

    // ---- exchange epilogue: smem round-trip -> row-major coalesced handling ----
    float* exs = (float*)sh;
    float* Cb = p.C; const float* bb = p.bias; int stride = p.Ntot; int cb = n0;
    if (p.mode == 0 && p.C1) {
        Cb = (blockIdx.x == 0) ? p.C : (blockIdx.x == 1 ? p.C1 : p.C2);
        bb = (blockIdx.x == 0) ? p.bias : (blockIdx.x == 1 ? p.bias1 : p.bias2);
        stride = HH; cb = 0;
    }

#pragma unroll
    for (int h = 0; h < 2; h++) {
        __syncthreads();
        if ((warp_m >> 1) == h) {
            int rbase = (warp_m & 1) * 32;
#pragma unroll
            for (int mt = 0; mt < 2; mt++)
#pragma unroll
            for (int hf = 0; hf < 2; hf++) {
                int rl = rbase + mt * 16 + hf * 8 + gID;
#pragma unroll
                for (int nt = 0; nt < 4; nt++) {
                    int ad = rl * 132 + warp_n * 32 + nt * 8 + tig * 2;
                    *(float2*)&exs[ad] =
                        make_float2(c[mt][nt][hf * 2], c[mt][nt][hf * 2 + 1]);
                }
            }
        }
        __syncthreads();
#pragma unroll
        for (int r = 0; r < 4; r++) {
            int rl = wid * 4 + r;
            int gm = m0 + h * 64 + rl;
            if (gm >= p.M) break;
            float4 v = *(float4*)&exs[rl * 132 + lid * 4];
            if (p.mode == 0) {
                int col = cb + lid * 4;
                if (bb) {
                    float4 b4 = *(const float4*)(bb + col);
                    v.x += b4.x; v.y += b4.y; v.z += b4.z; v.w += b4.w;
                }
                *(float4*)(Cb + (size_t)gm * stride + col) = v;
            } else if (p.mode == 1) {
                int sn = p.gidx[gm], d = p.dst[gm];
                float4 k4 = *(const float4*)(p.gsrc + (size_t)sn * HH + lid * 4);
                float4 q4 = *(const float4*)(p.Qm + (size_t)d * HH + lid * 4);
                float e0 = expf(q4.x * (v.x + k4.x));
                float e1 = expf(q4.y * (v.y + k4.y));
                float e2 = expf(q4.z * (v.z + k4.z));
                float e3 = expf(q4.w * (v.w + k4.w));
                *(float4*)(p.C + (size_t)gm * HH + lid * 4) =
                    make_float4(e0, e1, e2, e3);
                float* dr = p.den + (size_t)d * HH + lid * 4;
                atomicAdd(dr + 0, e0); atomicAdd(dr + 1, e1);
                atomicAdd(dr + 2, e2); atomicAdd(dr + 3, e3);
            } else {
                int sn = p.gidx[gm], d = p.dst[gm];
                float4 g4 = *(const float4*)(p.gsrc + (size_t)sn * HH + lid * 4);
                float4 e4 = *(const float4*)(p.ex + (size_t)gm * HH + lid * 4);
                float* ar = p.acc + (size_t)d * HH + lid * 4;
                atomicAdd(ar + 0, e4.x * (v.x + g4.x));
                atomicAdd(ar + 1, e4.y * (v.y + g4.y));
                atomicAdd(ar + 2, e4.z * (v.z + g4.z));
                atomicAdd(ar + 3, e4.w * (v.w + g4.w));
            }
        }
    }
}

// ---------------- tf32 pre-round streaming copy (GEMM-A sources) ----------------
__global__ __launch_bounds__(256) void round_copy_k(
    const float* __restrict__ in, float* __restrict__ out, int n4)
{
    int i = blockIdx.x * 256 + threadIdx.x;
    if (i >= n4) return;
    float4 v = ((const float4*)in)[i];
    ((float4*)out)[i] = make_float4(rnd(v.x), rnd(v.y), rnd(v.z), rnd(v.w));
}

// ---------------- fused weight transposes (tf32 pre-round + k-permute) ---------
struct TransDesc { const float* W; float* O; int srcN; int KB; int ldb; };
struct TransParams { TransDesc t[14]; int start[15]; };

__global__ void transpose_all_k(TransParams tp) {
    __shared__ float t[32][33];
    int b = blockIdx.x;
    int i = 0;
#pragma unroll
    for (int j = 0; j < 14; j++)
        if (b >= tp.start[j + 1]) i = j + 1;
    const TransDesc d = tp.t[i];
    int rem = b - tp.start[i];
    int ntk = d.KB >> 5;
    int tx = (rem % ntk) * 32;       // k tile
    int ty = (rem / ntk) * 32;       // n tile
#pragma unroll
    for (int r = 0; r < 4; r++) {
        int k = tx + threadIdx.y + r * 8, n = ty + threadIdx.x;
        t[threadIdx.y + r * 8][threadIdx.x] = d.W[(size_t)k * d.srcN + n];
    }
    __syncthreads();
#pragma unroll
    for (int r = 0; r < 4; r++) {
        int n = ty + threadIdx.y + r * 8, k = tx + threadIdx.x;
        d.O[(size_t)n * d.ldb + kperm(k)] =
            __uint_as_float(f2tf32(t[threadIdx.x][threadIdx.y + r * 8]));
    }
}

// ---------------- node div (float4, tf32-rounded output: GEMM-A consumer) ------
__global__ __launch_bounds__(256) void node_div_k(
    const float* __restrict__ den, const float* __restrict__ acc,
    float* __restrict__ out)
{
    int i = (blockIdx.x * 256 + threadIdx.x) * 4;
    if (i < NN * HH) {
        float4 d4 = *(const float4*)(den + i);
        float4 a4 = *(const float4*)(acc + i);
        float4 o;
        o.x = rnd((d4.x > 0.f) ? a4.x / d4.x : 0.f);
        o.y = rnd((d4.y > 0.f) ? a4.y / d4.y : 0.f);
        o.z = rnd((d4.z > 0.f) ? a4.z / d4.z : 0.f);
        o.w = rnd((d4.w > 0.f) ? a4.w / d4.w : 0.f);
        *(float4*)(out + i) = o;
    }
}

// ---------------- layernorm 128 (tf32-rounded output: GEMM-A consumer) ---------
__global__ __launch_bounds__(128) void ln128_k(
    const float* __restrict__ x, const float* __restrict__ g,
    const float* __restrict__ b, float* __restrict__ y)
{
    int row = blockIdx.x, t = threadIdx.x;
    float v = x[(size_t)row * 128 + t];
    float s = v, s2 = v * v;
#pragma unroll
    for (int o = 16; o > 0; o >>= 1) {
        s  += __shfl_xor_sync(0xffffffffu, s, o);
        s2 += __shfl_xor_sync(0xffffffffu, s2, o);
    }
    __shared__ float ws[4], ws2[4];
    int w = t >> 5, l = t & 31;
    if (l == 0) { ws[w] = s; ws2[w] = s2; }
    __syncthreads();
    s  = ws[0] + ws[1] + ws[2] + ws[3];
    s2 = ws2[0] + ws2[1] + ws2[2] + ws2[3];
    float mu  = s * (1.f / 128.f);
    float var = s2 * (1.f / 128.f) - mu * mu;
    float r = rsqrtf(var + 1e-5f);
    float hv = (v - mu) * r * g[t] + b[t];
    y[(size_t)row * 128 + t] = rnd(hv);
}

// ---------------- fused LN768 + gate + pool ----------------
#define LGP_BLOCKS 400
__global__ __launch_bounds__(256) void ln_gate_pool_k(
    const float* __restrict__ lin, const float* __restrict__ g,
    const float* __restrict__ b, const float* __restrict__ gw,
    const float* __restrict__ gb, float* __restrict__ Snum,
    float* __restrict__ S)
{
    __shared__ float ps[8 * 768];
    int wid = threadIdx.x >> 5, lid = threadIdx.x & 31;
    int gwarp = blockIdx.x * 8 + wid;
    const int NW = LGP_BLOCKS * 8;

    float accv[24];
#pragma unroll
    for (int i = 0; i < 24; i++) accv[i] = 0.f;
    float eacc = 0.f;
    float gbv = gb[0];

    for (int row = gwarp; row < NN; row += NW) {
        const float* xr = lin + (size_t)row * 768;
        float x[24];
        float s = 0.f, s2 = 0.f;
#pragma unroll
        for (int k = 0; k < 6; k++) {
            float4 v = *(const float4*)(xr + k * 128 + lid * 4);
            x[k * 4 + 0] = v.x; x[k * 4 + 1] = v.y;
            x[k * 4 + 2] = v.z; x[k * 4 + 3] = v.w;
            s += v.x + v.y + v.z + v.w;
            s2 += v.x * v.x + v.y * v.y + v.z * v.z + v.w * v.w;
        }
#pragma unroll
        for (int o = 16; o > 0; o >>= 1) {
            s  += __shfl_xor_sync(0xffffffffu, s, o);
            s2 += __shfl_xor_sync(0xffffffffu, s2, o);
        }
        float mu  = s * (1.f / 768.f);
        float var = s2 * (1.f / 768.f) - mu * mu;
        float r = rsqrtf(var + 1e-5f);
        float dot = 0.f;
#pragma unroll
        for (int k = 0; k < 6; k++) {
            int col = k * 128 + lid * 4;
            float4 g4 = *(const float4*)(g + col);
            float4 b4 = *(const float4*)(b + col);
            float4 w4 = *(const float4*)(gw + col);
            float h0 = (x[k * 4 + 0] - mu) * r * g4.x + b4.x;
            float h1 = (x[k * 4 + 1] - mu) * r * g4.y + b4.y;
            float h2 = (x[k * 4 + 2] - mu) * r * g4.z + b4.z;
            float h3 = (x[k * 4 + 3] - mu) * r * g4.w + b4.w;
            x[k * 4 + 0] = h0; x[k * 4 + 1] = h1;
            x[k * 4 + 2] = h2; x[k * 4 + 3] = h3;
            dot = fmaf(h0, w4.x, dot); dot = fmaf(h1, w4.y, dot);
            dot = fmaf(h2, w4.z, dot); dot = fmaf(h3, w4.w, dot);
        }
#pragma unroll
        for (int o = 16; o > 0; o >>= 1)
            dot += __shfl_xor_sync(0xffffffffu, dot, o);
        float e = expf(dot + gbv);
        eacc += e;
#pragma unroll
        for (int i = 0; i < 24; i++) accv[i] = fmaf(e, x[i], accv[i]);
    }

#pragma unroll
    for (int k = 0; k < 6; k++) {
        int col = k * 128 + lid * 4;
        *(float4*)&ps[wid * 768 + col] = make_float4(
            accv[k * 4 + 0], accv[k * 4 + 1], accv[k * 4 + 2], accv[k * 4 + 3]);
    }
    __syncthreads();
    for (int cidx = threadIdx.x; cidx < 768; cidx += 256) {
        float sum = 0.f;
#pragma unroll
        for (int w = 0; w < 8; w++) sum += ps[w * 768 + cidx];
        atomicAdd(Snum + cidx, sum);
    }
    if (lid == 0) atomicAdd(S, eacc);
}

__global__ void pool_norm_k(const float* __restrict__ Snum,
                            const float* __restrict__ S,
                            float* __restrict__ out) {
    int c = blockIdx.x * 256 + threadIdx.x;
    if (c < OUTD) out[c] = Snum[c] / S[0];
}

// ---------------- host ----------------
static void launch_tg(const TG& p) {
    dim3 grid(p.Ntot / 128, (p.M + 127) / 128);
    mma_gemm<<<grid, 512, GSMEM_BYTES>>>(p);
}

extern "C" void kernel_launch(void* const* d_in, const int* in_sizes, int n_in,
                              void* d_out, int out_size) {
    const float* kind   = (const float*)d_in[0];
    const float* edge_h = (const float*)d_in[1];
    const int*   src    = (const int*)  d_in[2];
    const int*   dst    = (const int*)  d_in[3];
    const float* KW  = (const float*)d_in[4];  const float* Kb  = (const float*)d_in[5];
    const float* VW  = (const float*)d_in[6];  const float* Vb  = (const float*)d_in[7];
    const float* QW  = (const float*)d_in[8];  const float* Qb  = (const float*)d_in[9];
    const float* WW  = (const float*)d_in[10]; const float* Wb  = (const float*)d_in[11];
    const float* K2W = (const float*)d_in[12]; const float* K2b = (const float*)d_in[13];
    const float* V2W = (const float*)d_in[14]; const float* V2b = (const float*)d_in[15];
    const float* Q2W = (const float*)d_in[16]; const float* Q2b = (const float*)d_in[17];
    const float* W2W = (const float*)d_in[18]; const float* W2b = (const float*)d_in[19];
    const float* ln1g = (const float*)d_in[20]; const float* ln1b = (const float*)d_in[21];
    const float* ln2g = (const float*)d_in[22]; const float* ln2b = (const float*)d_in[23];
    const float* gw  = (const float*)d_in[24]; const float* gb  = (const float*)d_in[25];
    float* out = (float*)d_out;

    static float *pQ = nullptr, *pnK, *pnV, *pex, *pehR, *pkR, *pden, *pacc,
                 *phn, *ph, *plin, *pSnum, *pS, *pBt;
    if (!pQ) {
        cudaGetSymbolAddress((void**)&pQ,   g_Q);
        cudaGetSymbolAddress((void**)&pnK,  g_nK);
        cudaGetSymbolAddress((void**)&pnV,  g_nV);
        cudaGetSymbolAddress((void**)&pex,  g_ex);
        cudaGetSymbolAddress((void**)&pehR, g_ehR);
        cudaGetSymbolAddress((void**)&pkR,  g_kR);
        cudaGetSymbolAddress((void**)&pden, g_den);
        cudaGetSymbolAddress((void**)&pacc, g_acc);
        cudaGetSymbolAddress((void**)&phn,  g_hn);
        cudaGetSymbolAddress((void**)&ph,   g_h);
        cudaGetSymbolAddress((void**)&plin, g_lin);
        cudaGetSymbolAddress((void**)&pSnum, g_Snum);
        cudaGetSymbolAddress((void**)&pS,   g_S);
        cudaGetSymbolAddress((void**)&pBt,  g_Bt);
        cudaFuncSetAttribute(mma_gemm, cudaFuncAttributeMaxDynamicSharedMemorySize,
                             GSMEM_BYTES);
    }

    // packed transposed-weight offsets (floats)
    const int oN1  = 0;        // [384,128]: Q | nodeK | nodeV
    const int oKe1 = 49152;    // [128,128]: KW edge part
    const int oVe1 = 65536;    // [128,128]: VW edge part
    const int oW1  = 81920;    // [128,256]: WW full
    const int oN2  = 114688;   // [384,256]: Q2 | K2 node | V2 node
    const int oKe2 = 212992;   // [128,128]: K2W edge part
    const int oVe2 = 229376;   // [128,128]: V2W edge part
    const int oW2  = 245760;   // [768,384]: W2W full

    TransParams tp;
    tp.t[0]  = {QW,                pBt + oN1,             128, 128, 128};
    tp.t[1]  = {KW,                pBt + oN1 + 128 * 128, 128, 128, 128};
    tp.t[2]  = {VW,                pBt + oN1 + 256 * 128, 128, 128, 128};
    tp.t[3]  = {KW + 128 * 128,    pBt + oKe1,            128, 128, 128};
    tp.t[4]  = {VW + 128 * 128,    pBt + oVe1,            128, 128, 128};
    tp.t[5]  = {WW,                pBt + oW1,             128, 256, 256};
    tp.t[6]  = {Q2W,               pBt + oN2,             128, 256, 256};
    tp.t[7]  = {K2W,               pBt + oN2 + 128 * 256,       128, 128, 256};
    tp.t[8]  = {K2W + 256 * 128,   pBt + oN2 + 128 * 256 + 128, 128, 128, 256};
    tp.t[9]  = {V2W,               pBt + oN2 + 256 * 256,       128, 128, 256};
    tp.t[10] = {V2W + 256 * 128,   pBt + oN2 + 256 * 256 + 128, 128, 128, 256};
    tp.t[11] = {K2W + 128 * 128,   pBt + oKe2,            128, 128, 128};
    tp.t[12] = {V2W + 128 * 128,   pBt + oVe2,            128, 128, 128};
    tp.t[13] = {W2W,               pBt + oW2,             768, 384, 384};
    int s = 0;
    for (int i = 0; i < 14; i++) {
        tp.start[i] = s;
        s += (tp.t[i].srcN >> 5) * (tp.t[i].KB >> 5);
    }
    tp.start[14] = s;
    transpose_all_k<<<s, dim3(32, 8)>>>(tp);

    // pre-round GEMM-A sources (plain streaming, no permute)
    round_copy_k<<<(NN * FF / 4 + 255) / 256, 256>>>(kind, pkR, NN * FF / 4);
    round_copy_k<<<(EE * HH / 4 + 255) / 256, 256>>>(edge_h, pehR, EE * HH / 4);

    const size_t nh_bytes = (size_t)NN * HH * sizeof(float);
    TG p;

    // ===================== layer 1 =====================
    cudaMemsetAsync(pden, 0, nh_bytes);
    cudaMemsetAsync(pacc, 0, nh_bytes);

    // fused node GEMM: Q | nodeK | nodeV = kind @ {QW, KW[0:F], VW[0:F]}
    p = {pkR, nullptr, nullptr, FF, 0, 0, 0, 0, 0, 128, pBt + oN1,
         Qb, nullptr, nullptr, pQ, NN, 384, 0,
         nullptr, nullptr, nullptr, nullptr, nullptr,
         pnK, pnV, Kb, Vb};
    launch_tg(p);
    // eK fused: ex = exp(Q[dst] * (edge_h@KWe + nodeK[src])); den[dst]+=ex
    p = {pehR, nullptr, nullptr, FF, 0, 0, 0, 0, 0, 128, pBt + oKe1,
         nullptr, src, pnK, pex, EE, HH, 1,
         dst, pQ, pden, nullptr, nullptr,
         nullptr, nullptr, nullptr, nullptr};
    launch_tg(p);
    // eV fused: acc[dst] += ex * (edge_h@VWe + nodeV[src])
    p = {pehR, nullptr, nullptr, FF, 0, 0, 0, 0, 0, 128, pBt + oVe1,
         nullptr, src, pnV, nullptr, EE, HH, 2,
         dst, nullptr, nullptr, pacc, pex,
         nullptr, nullptr, nullptr, nullptr};
    launch_tg(p);

    node_div_k<<<(NN * HH / 4 + 255) / 256, 256>>>(pden, pacc, phn);

    // lin1 = concat(h_n, kind) @ WW + Wb ; h = LN(lin1)
    p = {phn, pkR, nullptr, HH, FF, 0, 0, HH, 0, 256, pBt + oW1,
         Wb, nullptr, nullptr, plin, NN, HH, 0,
         nullptr, nullptr, nullptr, nullptr, nullptr,
         nullptr, nullptr, nullptr, nullptr};
    launch_tg(p);
    ln128_k<<<NN, 128>>>(plin, ln1g, ln1b, ph);

    // ===================== layer 2 =====================
    cudaMemsetAsync(pden, 0, nh_bytes);
    cudaMemsetAsync(pacc, 0, nh_bytes);

    // fused node GEMM: Q2 | nodeK2 | nodeV2 = [kind,h] @ packed
    p = {pkR, ph, nullptr, FF, HH, 0, 0, 128, 0, 256, pBt + oN2,
         Q2b, nullptr, nullptr, pQ, NN, 384, 0,
         nullptr, nullptr, nullptr, nullptr, nullptr,
         pnK, pnV, K2b, V2b};
    launch_tg(p);
    // eK2
    p = {pehR, nullptr, nullptr, FF, 0, 0, 0, 0, 0, 128, pBt + oKe2,
         nullptr, src, pnK, pex, EE, HH, 1,
         dst, pQ, pden, nullptr, nullptr,
         nullptr, nullptr, nullptr, nullptr};
    launch_tg(p);
    // eV2
    p = {pehR, nullptr, nullptr, FF, 0, 0, 0, 0, 0, 128, pBt + oVe2,
         nullptr, src, pnV, nullptr, EE, HH, 2,
         dst, nullptr, nullptr, pacc, pex,
         nullptr, nullptr, nullptr, nullptr};
    launch_tg(p);

    node_div_k<<<(NN * HH / 4 + 255) / 256, 256>>>(pden, pacc, phn);

    // lin2 = concat(h_n1, h, kind) @ W2W + W2b (LN fused below)
    p = {phn, ph, pkR, HH, HH, FF, 0, HH, 2 * HH, 384, pBt + oW2,
         W2b, nullptr, nullptr, plin, NN, OUTD, 0,
         nullptr, nullptr, nullptr, nullptr, nullptr,
         nullptr, nullptr, nullptr, nullptr};
    launch_tg(p);

    // ===================== fused LN + gate + pool =====================
    cudaMemsetAsync(pSnum, 0, OUTD * sizeof(float));
    cudaMemsetAsync(pS, 0, sizeof(float));
    ln_gate_pool_k<<<LGP_BLOCKS, 256>>>(plin, ln2g, ln2b, gw, gb, pSnum, pS);
    pool_norm_k<<<3, 256>>>(pSnum, pS, out);
}

// round 16
// speedup vs baseline: 1.1908x; 1.0466x over previous
#include <cuda_runtime.h>
#include <math.h>
#include <stdint.h>

#define NN 50000
#define EE 500000
#define FF 128
#define HH 128
#define OUTD 768

// ---------------- scratch (device globals: no allocation allowed) ----------------
__device__ float g_Q  [(size_t)NN * HH];
__device__ float g_nK [(size_t)NN * HH];
__device__ float g_nV [(size_t)NN * HH];
__device__ float g_ex [(size_t)EE * HH];    // per-edge exp(Q[dst]*eK)
__device__ float g_kR [(size_t)NN * FF];    // kind, tf32-pre-rounded
__device__ float g_den[(size_t)NN * HH];
__device__ float g_acc[(size_t)NN * HH];
__device__ float g_hn [(size_t)NN * HH];    // tf32-pre-rounded at producer
__device__ float g_h  [(size_t)NN * HH];    // tf32-pre-rounded at producer
__device__ float g_lin[(size_t)NN * OUTD];
__device__ float g_Snum[OUTD];
__device__ float g_S[1];
__device__ float g_Bt[540672];   // packed transposed weights (tf32, k-permuted)

// ---------------- helpers ----------------
__device__ __forceinline__ uint32_t smem_u32(const void* p) {
    uint32_t a;
    asm("{ .reg .u64 t; cvta.to.shared.u64 t, %1; cvt.u32.u64 %0, t; }" : "=r"(a) : "l"(p));
    return a;
}
__device__ __forceinline__ uint32_t f2tf32(float x) {
    uint32_t u;
    asm("cvt.rna.tf32.f32 %0, %1;" : "=r"(u) : "f"(x));
    return u;
}
__device__ __forceinline__ float rnd(float x) { return __uint_as_float(f2tf32(x)); }
__device__ __forceinline__ void mma1688(float* c, const uint32_t* a,
                                        uint32_t b0, uint32_t b1) {
    asm volatile(
        "mma.sync.aligned.m16n8k8.row.col.f32.tf32.tf32.f32 "
        "{%0,%1,%2,%3}, {%4,%5,%6,%7}, {%8,%9}, {%0,%1,%2,%3};"
        : "+f"(c[0]), "+f"(c[1]), "+f"(c[2]), "+f"(c[3])
        : "r"(a[0]), "r"(a[1]), "r"(a[2]), "r"(a[3]), "r"(b0), "r"(b1));
}
__device__ __forceinline__ void cp16(uint32_t dst, const void* src, int szn) {
    asm volatile("cp.async.ca.shared.global [%0], [%1], 16, %2;"
                 :: "r"(dst), "l"(src), "r"(szn) : "memory");
}
__device__ __forceinline__ void cpa_commit() {
    asm volatile("cp.async.commit_group;" ::: "memory");
}
template <int N> __device__ __forceinline__ void cpa_wait() {
    asm volatile("cp.async.wait_group %0;" :: "n"(N) : "memory");
}

#define PADKA 20   // A smem stride (floats): conflict-free for scalar LDS
#define PADKB 24   // B smem stride (floats): conflict-free for LDS.64 (gID*12+tig)

// k-permutation within each 8-block (B ONLY): position 2t <- k=t, 2t+1 <- k=t+4
__device__ __forceinline__ int kperm(int k) {
    return (k & ~7) + ((k & 4) ? ((k & 3) * 2 + 1) : ((k & 3) * 2));
}

// ================= tf32 mma GEMM (512 thr, 32x32 warp tiles) ===================
// C = concat_k(A0,A1,A2) @ Bt^T. Bt [Ntot, ldb] K-major PRE-ROUNDED + k-PERMUTED.
// CVTA=1: A raw fp32 (cvt in-loop). CVTA=0: A pre-rounded tf32.
// mode 0: C = gemm + bias. If C1 set: blockIdx.x picks C/C1/C2 (+bias1/2), [M,128].
// mode 1: v = gemm + nK[src]; ex = exp(Q[dst]*v); C = ex; den[dst] += ex
// mode 2: v = gemm + nV[src]; acc[dst] += ex[row]*v (no C write)
struct TG {
    const float* A0; const float* A1; const float* A2;
    int k0, k1, k2;
    int bc0, bc1, bc2;
    int ldb;
    const float* Bt;
    const float* bias;
    const int* gidx; const float* gsrc;
    float* C; int M, Ntot;
    int mode;
    const int* dst; const float* Qm; float* den; float* acc; const float* ex;
    float* C1; float* C2; const float* bias1; const float* bias2;
};

#define A_ST 2560                     // 128*20 u32 per A stage
#define B_ST 3072                     // 128*24 u32 per B stage
#define GSMEM_BYTES ((3 * A_ST + 3 * B_ST) * 4)   // 67584; exchange needs 33792

template <int CVTA>
__global__ __launch_bounds__(512, 2) void mma_gemm(TG p) {
    extern __shared__ uint32_t sh[];
    const uint32_t sbase = smem_u32(sh);

    const int tid = threadIdx.x;
    const int lid = tid & 31, wid = tid >> 5;       // 16 warps
    const int warp_m = wid & 3, warp_n = wid >> 2;  // 4 x 4, 32x32 per warp
    const int gID = lid >> 2, tig = lid & 3;
    const int m0 = blockIdx.y * 128, n0 = blockIdx.x * 128;

    float c[2][4][4];
#pragma unroll
    for (int mt = 0; mt < 2; mt++)
#pragma unroll
        for (int nt = 0; nt < 4; nt++)
#pragma unroll
            for (int i = 0; i < 4; i++) c[mt][nt][i] = 0.f;

    const int K = p.k0 + p.k1 + p.k2;
    const int nch = K >> 4;

    auto load_chunk = [&](int kb) {
        int off = kb << 4;
        const float* A; int lda; int bc;
        if (off < p.k0)             { A = p.A0; lda = p.k0; bc = p.bc0; }
        else if (off < p.k0 + p.k1) { A = p.A1; lda = p.k1; bc = p.bc1; off -= p.k0; }
        else                        { A = p.A2; lda = p.k2; bc = p.bc2; off -= p.k0 + p.k1; }
        int st = kb % 3;
        uint32_t ab = sbase + st * (A_ST * 4);
        uint32_t bb = sbase + (3 * A_ST + st * B_ST) * 4;
        int row = tid >> 2, kq = tid & 3;
        int gm = m0 + row;
        int gmc = gm < p.M ? gm : p.M - 1;
        cp16(ab + row * 80 + kq * 16,
             A + (size_t)gmc * lda + off + kq * 4, gm < p.M ? 16 : 0);
        cp16(bb + row * 96 + kq * 16,
             p.Bt + (size_t)(n0 + row) * p.ldb + bc + off + kq * 4, 16);
        cpa_commit();
    };

    load_chunk(0);
    load_chunk(1);

    for (int kb = 0; kb < nch; kb++) {
        if (kb + 2 < nch) load_chunk(kb + 2);
        int np = nch - kb - 1; if (np > 2) np = 2;
        if (np == 2) cpa_wait<2>();
        else if (np == 1) cpa_wait<1>();
        else cpa_wait<0>();
        __syncthreads();

        int st = kb % 3;
        const uint32_t* shA = sh + st * A_ST;
        const uint32_t* shB = sh + 3 * A_ST + st * B_ST;
#pragma unroll
        for (int k8 = 0; k8 < 16; k8 += 8) {
            uint32_t a[2][4];
#pragma unroll
            for (int mt = 0; mt < 2; mt++) {
                int rb = (warp_m * 32 + mt * 16 + gID) * PADKA + k8 + tig;
                if (CVTA) {
                    a[mt][0] = f2tf32(__uint_as_float(shA[rb]));
                    a[mt][1] = f2tf32(__uint_as_float(shA[rb + 8 * PADKA]));
                    a[mt][2] = f2tf32(__uint_as_float(shA[rb + 4]));
                    a[mt][3] = f2tf32(__uint_as_float(shA[rb + 8 * PADKA + 4]));
                } else {
                    a[mt][0] = shA[rb];
                    a[mt][1] = shA[rb + 8 * PADKA];
                    a[mt][2] = shA[rb + 4];
                    a[mt][3] = shA[rb + 8 * PADKA + 4];
                }
            }
#pragma unroll
            for (int nt = 0; nt < 4; nt++) {
                // B permuted: positions (2tig, 2tig+1) = logical k (tig, tig+4)
                int nb = (warp_n * 32 + nt * 8 + gID) * PADKB + k8 + 2 * tig;
                uint2 b = *(const uint2*)&shB[nb];
#pragma unroll
                for (int mt = 0; mt < 2; mt++)
                    mma1688(c[mt][nt], a[mt], b.x, b.y);
            }
        }
        __syncthreads();
    }

    // ---- exchange epilogue: smem round-trip -> row-major coalesced handling ----
    float* exs = (float*)sh;
    float* Cb = p.C; const float* bb = p.bias; int stride = p.Ntot; int cb = n0;
    if (p.mode == 0 && p.C1) {
        Cb = (blockIdx.x == 0) ? p.C : (blockIdx.x == 1 ? p.C1 : p.C2);
        bb = (blockIdx.x == 0) ? p.bias : (blockIdx.x == 1 ? p.bias1 : p.bias2);
        stride = HH; cb = 0;
    }

#pragma unroll
    for (int h = 0; h < 2; h++) {
        __syncthreads();
        if ((warp_m >> 1) == h) {
            int rbase = (warp_m & 1) * 32;
#pragma unroll
            for (int mt = 0; mt < 2; mt++)
#pragma unroll
            for (int hf = 0; hf < 2; hf++) {
                int rl = rbase + mt * 16 + hf * 8 + gID;
#pragma unroll
                for (int nt = 0; nt < 4; nt++) {
                    int ad = rl * 132 + warp_n * 32 + nt * 8 + tig * 2;
                    *(float2*)&exs[ad] =
                        make_float2(c[mt][nt][hf * 2], c[mt][nt][hf * 2 + 1]);
                }
            }
        }
        __syncthreads();
#pragma unroll
        for (int r = 0; r < 4; r++) {
            int rl = wid * 4 + r;
            int gm = m0 + h * 64 + rl;
            if (gm >= p.M) break;
            float4 v = *(float4*)&exs[rl * 132 + lid * 4];
            if (p.mode == 0) {
                int col = cb + lid * 4;
                if (bb) {
                    float4 b4 = *(const float4*)(bb + col);
                    v.x += b4.x; v.y += b4.y; v.z += b4.z; v.w += b4.w;
                }
                *(float4*)(Cb + (size_t)gm * stride + col) = v;
            } else if (p.mode == 1) {
                int sn = p.gidx[gm], d = p.dst[gm];
                float4 k4 = *(const float4*)(p.gsrc + (size_t)sn * HH + lid * 4);
                float4 q4 = *(const float4*)(p.Qm + (size_t)d * HH + lid * 4);
                float e0 = expf(q4.x * (v.x + k4.x));
                float e1 = expf(q4.y * (v.y + k4.y));
                float e2 = expf(q4.z * (v.z + k4.z));
                float e3 = expf(q4.w * (v.w + k4.w));
                *(float4*)(p.C + (size_t)gm * HH + lid * 4) =
                    make_float4(e0, e1, e2, e3);
                float* dr = p.den + (size_t)d * HH + lid * 4;
                atomicAdd(dr + 0, e0); atomicAdd(dr + 1, e1);
                atomicAdd(dr + 2, e2); atomicAdd(dr + 3, e3);
            } else {
                int sn = p.gidx[gm], d = p.dst[gm];
                float4 g4 = *(const float4*)(p.gsrc + (size_t)sn * HH + lid * 4);
                float4 e4 = *(const float4*)(p.ex + (size_t)gm * HH + lid * 4);
                float* ar = p.acc + (size_t)d * HH + lid * 4;
                atomicAdd(ar + 0, e4.x * (v.x + g4.x));
                atomicAdd(ar + 1, e4.y * (v.y + g4.y));
                atomicAdd(ar + 2, e4.z * (v.z + g4.z));
                atomicAdd(ar + 3, e4.w * (v.w + g4.w));
            }
        }
    }
}

// ---------------- tf32 pre-round streaming copy (cheap GEMM-A sources) ---------
__global__ __launch_bounds__(256) void round_copy_k(
    const float* __restrict__ in, float* __restrict__ out, int n4)
{
    int i = blockIdx.x * 256 + threadIdx.x;
    if (i >= n4) return;
    float4 v = ((const float4*)in)[i];
    ((float4*)out)[i] = make_float4(rnd(v.x), rnd(v.y), rnd(v.z), rnd(v.w));
}

// ---------------- fused weight transposes (tf32 pre-round + k-permute) ---------
struct TransDesc { const float* W; float* O; int srcN; int KB; int ldb; };
struct TransParams { TransDesc t[14]; int start[15]; };

__global__ void transpose_all_k(TransParams tp) {
    __shared__ float t[32][33];
    int b = blockIdx.x;
    int i = 0;
#pragma unroll
    for (int j = 0; j < 14; j++)
        if (b >= tp.start[j + 1]) i = j + 1;
    const TransDesc d = tp.t[i];
    int rem = b - tp.start[i];
    int ntk = d.KB >> 5;
    int tx = (rem % ntk) * 32;       // k tile
    int ty = (rem / ntk) * 32;       // n tile
#pragma unroll
    for (int r = 0; r < 4; r++) {
        int k = tx + threadIdx.y + r * 8, n = ty + threadIdx.x;
        t[threadIdx.y + r * 8][threadIdx.x] = d.W[(size_t)k * d.srcN + n];
    }
    __syncthreads();
#pragma unroll
    for (int r = 0; r < 4; r++) {
        int n = ty + threadIdx.y + r * 8, k = tx + threadIdx.x;
        d.O[(size_t)n * d.ldb + kperm(k)] =
            __uint_as_float(f2tf32(t[threadIdx.x][threadIdx.y + r * 8]));
    }
}

// ---------------- node div (float4, tf32-rounded output: GEMM-A consumer) ------
__global__ __launch_bounds__(256) void node_div_k(
    const float* __restrict__ den, const float* __restrict__ acc,
    float* __restrict__ out)
{
    int i = (blockIdx.x * 256 + threadIdx.x) * 4;
    if (i < NN * HH) {
        float4 d4 = *(const float4*)(den + i);
        float4 a4 = *(const float4*)(acc + i);
        float4 o;
        o.x = rnd((d4.x > 0.f) ? a4.x / d4.x : 0.f);
        o.y = rnd((d4.y > 0.f) ? a4.y / d4.y : 0.f);
        o.z = rnd((d4.z > 0.f) ? a4.z / d4.z : 0.f);
        o.w = rnd((d4.w > 0.f) ? a4.w / d4.w : 0.f);
        *(float4*)(out + i) = o;
    }
}

// ---------------- layernorm 128 (tf32-rounded output: GEMM-A consumer) ---------
__global__ __launch_bounds__(128) void ln128_k(
    const float* __restrict__ x, const float* __restrict__ g,
    const float* __restrict__ b, float* __restrict__ y)
{
    int row = blockIdx.x, t = threadIdx.x;
    float v = x[(size_t)row * 128 + t];
    float s = v, s2 = v * v;
#pragma unroll
    for (int o = 16; o > 0; o >>= 1) {
        s  += __shfl_xor_sync(0xffffffffu, s, o);
        s2 += __shfl_xor_sync(0xffffffffu, s2, o);
    }
    __shared__ float ws[4], ws2[4];
    int w = t >> 5, l = t & 31;
    if (l == 0) { ws[w] = s; ws2[w] = s2; }
    __syncthreads();
    s  = ws[0] + ws[1] + ws[2] + ws[3];
    s2 = ws2[0] + ws2[1] + ws2[2] + ws2[3];
    float mu  = s * (1.f / 128.f);
    float var = s2 * (1.f / 128.f) - mu * mu;
    float r = rsqrtf(var + 1e-5f);
    float hv = (v - mu) * r * g[t] + b[t];
    y[(size_t)row * 128 + t] = rnd(hv);
}

// ---------------- fused LN768 + gate + pool ----------------
#define LGP_BLOCKS 400
__global__ __launch_bounds__(256) void ln_gate_pool_k(
    const float* __restrict__ lin, const float* __restrict__ g,
    const float* __restrict__ b, const float* __restrict__ gw,
    const float* __restrict__ gb, float* __restrict__ Snum,
    float* __restrict__ S)
{
    __shared__ float ps[8 * 768];
    int wid = threadIdx.x >> 5, lid = threadIdx.x & 31;
    int gwarp = blockIdx.x * 8 + wid;
    const int NW = LGP_BLOCKS * 8;

    float accv[24];
#pragma unroll
    for (int i = 0; i < 24; i++) accv[i] = 0.f;
    float eacc = 0.f;
    float gbv = gb[0];

    for (int row = gwarp; row < NN; row += NW) {
        const float* xr = lin + (size_t)row * 768;
        float x[24];
        float s = 0.f, s2 = 0.f;
#pragma unroll
        for (int k = 0; k < 6; k++) {
            float4 v = *(const float4*)(xr + k * 128 + lid * 4);
            x[k * 4 + 0] = v.x; x[k * 4 + 1] = v.y;
            x[k * 4 + 2] = v.z; x[k * 4 + 3] = v.w;
            s += v.x + v.y + v.z + v.w;
            s2 += v.x * v.x + v.y * v.y + v.z * v.z + v.w * v.w;
        }
#pragma unroll
        for (int o = 16; o > 0; o >>= 1) {
            s  += __shfl_xor_sync(0xffffffffu, s, o);
            s2 += __shfl_xor_sync(0xffffffffu, s2, o);
        }
        float mu  = s * (1.f / 768.f);
        float var = s2 * (1.f / 768.f) - mu * mu;
        float r = rsqrtf(var + 1e-5f);
        float dot = 0.f;
#pragma unroll
        for (int k = 0; k < 6; k++) {
            int col = k * 128 + lid * 4;
            float4 g4 = *(const float4*)(g + col);
            float4 b4 = *(const float4*)(b + col);
            float4 w4 = *(const float4*)(gw + col);
            float h0 = (x[k * 4 + 0] - mu) * r * g4.x + b4.x;
            float h1 = (x[k * 4 + 1] - mu) * r * g4.y + b4.y;
            float h2 = (x[k * 4 + 2] - mu) * r * g4.z + b4.z;
            float h3 = (x[k * 4 + 3] - mu) * r * g4.w + b4.w;
            x[k * 4 + 0] = h0; x[k * 4 + 1] = h1;
            x[k * 4 + 2] = h2; x[k * 4 + 3] = h3;
            dot = fmaf(h0, w4.x, dot); dot = fmaf(h1, w4.y, dot);
            dot = fmaf(h2, w4.z, dot); dot = fmaf(h3, w4.w, dot);
        }
#pragma unroll
        for (int o = 16; o > 0; o >>= 1)
            dot += __shfl_xor_sync(0xffffffffu, dot, o);
        float e = expf(dot + gbv);
        eacc += e;
#pragma unroll
        for (int i = 0; i < 24; i++) accv[i] = fmaf(e, x[i], accv[i]);
    }

#pragma unroll
    for (int k = 0; k < 6; k++) {
        int col = k * 128 + lid * 4;
        *(float4*)&ps[wid * 768 + col] = make_float4(
            accv[k * 4 + 0], accv[k * 4 + 1], accv[k * 4 + 2], accv[k * 4 + 3]);
    }
    __syncthreads();
    for (int cidx = threadIdx.x; cidx < 768; cidx += 256) {
        float sum = 0.f;
#pragma unroll
        for (int w = 0; w < 8; w++) sum += ps[w * 768 + cidx];
        atomicAdd(Snum + cidx, sum);
    }
    if (lid == 0) atomicAdd(S, eacc);
}

__global__ void pool_norm_k(const float* __restrict__ Snum,
                            const float* __restrict__ S,
                            float* __restrict__ out) {
    int c = blockIdx.x * 256 + threadIdx.x;
    if (c < OUTD) out[c] = Snum[c] / S[0];
}

// ---------------- host ----------------
static void launch_tg(const TG& p, bool cvtA) {
    dim3 grid(p.Ntot / 128, (p.M + 127) / 128);
    if (cvtA) mma_gemm<1><<<grid, 512, GSMEM_BYTES>>>(p);
    else      mma_gemm<0><<<grid, 512, GSMEM_BYTES>>>(p);
}

extern "C" void kernel_launch(void* const* d_in, const int* in_sizes, int n_in,
                              void* d_out, int out_size) {
    const float* kind   = (const float*)d_in[0];
    const float* edge_h = (const float*)d_in[1];
    const int*   src    = (const int*)  d_in[2];
    const int*   dst    = (const int*)  d_in[3];
    const float* KW  = (const float*)d_in[4];  const float* Kb  = (const float*)d_in[5];
    const float* VW  = (const float*)d_in[6];  const float* Vb  = (const float*)d_in[7];
    const float* QW  = (const float*)d_in[8];  const float* Qb  = (const float*)d_in[9];
    const float* WW  = (const float*)d_in[10]; const float* Wb  = (const float*)d_in[11];
    const float* K2W = (const float*)d_in[12]; const float* K2b = (const float*)d_in[13];
    const float* V2W = (const float*)d_in[14]; const float* V2b = (const float*)d_in[15];
    const float* Q2W = (const float*)d_in[16]; const float* Q2b = (const float*)d_in[17];
    const float* W2W = (const float*)d_in[18]; const float* W2b = (const float*)d_in[19];
    const float* ln1g = (const float*)d_in[20]; const float* ln1b = (const float*)d_in[21];
    const float* ln2g = (const float*)d_in[22]; const float* ln2b = (const float*)d_in[23];
    const float* gw  = (const float*)d_in[24]; const float* gb  = (const float*)d_in[25];
    float* out = (float*)d_out;

    static float *pQ = nullptr, *pnK, *pnV, *pex, *pkR, *pden, *pacc,
                 *phn, *ph, *plin, *pSnum, *pS, *pBt;
    if (!pQ) {
        cudaGetSymbolAddress((void**)&pQ,   g_Q);
        cudaGetSymbolAddress((void**)&pnK,  g_nK);
        cudaGetSymbolAddress((void**)&pnV,  g_nV);
        cudaGetSymbolAddress((void**)&pex,  g_ex);
        cudaGetSymbolAddress((void**)&pkR,  g_kR);
        cudaGetSymbolAddress((void**)&pden, g_den);
        cudaGetSymbolAddress((void**)&pacc, g_acc);
        cudaGetSymbolAddress((void**)&phn,  g_hn);
        cudaGetSymbolAddress((void**)&ph,   g_h);
        cudaGetSymbolAddress((void**)&plin, g_lin);
        cudaGetSymbolAddress((void**)&pSnum, g_Snum);
        cudaGetSymbolAddress((void**)&pS,   g_S);
        cudaGetSymbolAddress((void**)&pBt,  g_Bt);
        cudaFuncSetAttribute(mma_gemm<0>, cudaFuncAttributeMaxDynamicSharedMemorySize,
                             GSMEM_BYTES);
        cudaFuncSetAttribute(mma_gemm<1>, cudaFuncAttributeMaxDynamicSharedMemorySize,
                             GSMEM_BYTES);
    }

    // packed transposed-weight offsets (floats)
    const int oN1  = 0;        // [384,128]: Q | nodeK | nodeV
    const int oKe1 = 49152;    // [128,128]: KW edge part
    const int oVe1 = 65536;    // [128,128]: VW edge part
    const int oW1  = 81920;    // [128,256]: WW full
    const int oN2  = 114688;   // [384,256]: Q2 | K2 node | V2 node
    const int oKe2 = 212992;   // [128,128]: K2W edge part
    const int oVe2 = 229376;   // [128,128]: V2W edge part
    const int oW2  = 245760;   // [768,384]: W2W full

    TransParams tp;
    tp.t[0]  = {QW,                pBt + oN1,             128, 128, 128};
    tp.t[1]  = {KW,                pBt + oN1 + 128 * 128, 128, 128, 128};
    tp.t[2]  = {VW,                pBt + oN1 + 256 * 128, 128, 128, 128};
    tp.t[3]  = {KW + 128 * 128,    pBt + oKe1,            128, 128, 128};
    tp.t[4]  = {VW + 128 * 128,    pBt + oVe1,            128, 128, 128};
    tp.t[5]  = {WW,                pBt + oW1,             128, 256, 256};
    tp.t[6]  = {Q2W,               pBt + oN2,             128, 256, 256};
    tp.t[7]  = {K2W,               pBt + oN2 + 128 * 256,       128, 128, 256};
    tp.t[8]  = {K2W + 256 * 128,   pBt + oN2 + 128 * 256 + 128, 128, 128, 256};
    tp.t[9]  = {V2W,               pBt + oN2 + 256 * 256,       128, 128, 256};
    tp.t[10] = {V2W + 256 * 128,   pBt + oN2 + 256 * 256 + 128, 128, 128, 256};
    tp.t[11] = {K2W + 128 * 128,   pBt + oKe2,            128, 128, 128};
    tp.t[12] = {V2W + 128 * 128,   pBt + oVe2,            128, 128, 128};
    tp.t[13] = {W2W,               pBt + oW2,             768, 384, 384};
    int s = 0;
    for (int i = 0; i < 14; i++) {
        tp.start[i] = s;
        s += (tp.t[i].srcN >> 5) * (tp.t[i].KB >> 5);
    }
    tp.start[14] = s;
    transpose_all_k<<<s, dim3(32, 8)>>>(tp);

    // pre-round kind only (cheap, reused in 4 GEMMs); edge_h stays raw (CVTA=1)
    round_copy_k<<<(NN * FF / 4 + 255) / 256, 256>>>(kind, pkR, NN * FF / 4);

    const size_t nh_bytes = (size_t)NN * HH * sizeof(float);
    TG p;

    // ===================== layer 1 =====================
    cudaMemsetAsync(pden, 0, nh_bytes);
    cudaMemsetAsync(pacc, 0, nh_bytes);

    // fused node GEMM: Q | nodeK | nodeV = kind @ {QW, KW[0:F], VW[0:F]}
    p = {pkR, nullptr, nullptr, FF, 0, 0, 0, 0, 0, 128, pBt + oN1,
         Qb, nullptr, nullptr, pQ, NN, 384, 0,
         nullptr, nullptr, nullptr, nullptr, nullptr,
         pnK, pnV, Kb, Vb};
    launch_tg(p, false);
    // eK fused: ex = exp(Q[dst] * (edge_h@KWe + nodeK[src])); den[dst]+=ex
    p = {edge_h, nullptr, nullptr, FF, 0, 0, 0, 0, 0, 128, pBt + oKe1,
         nullptr, src, pnK, pex, EE, HH, 1,
         dst, pQ, pden, nullptr, nullptr,
         nullptr, nullptr, nullptr, nullptr};
    launch_tg(p, true);
    // eV fused: acc[dst] += ex * (edge_h@VWe + nodeV[src])
    p = {edge_h, nullptr, nullptr, FF, 0, 0, 0, 0, 0, 128, pBt + oVe1,
         nullptr, src, pnV, nullptr, EE, HH, 2,
         dst, nullptr, nullptr, pacc, pex,
         nullptr, nullptr, nullptr, nullptr};
    launch_tg(p, true);

    node_div_k<<<(NN * HH / 4 + 255) / 256, 256>>>(pden, pacc, phn);

    // lin1 = concat(h_n, kind) @ WW + Wb ; h = LN(lin1)
    p = {phn, pkR, nullptr, HH, FF, 0, 0, HH, 0, 256, pBt + oW1,
         Wb, nullptr, nullptr, plin, NN, HH, 0,
         nullptr, nullptr, nullptr, nullptr, nullptr,
         nullptr, nullptr, nullptr, nullptr};
    launch_tg(p, false);
    ln128_k<<<NN, 128>>>(plin, ln1g, ln1b, ph);

    // ===================== layer 2 =====================
    cudaMemsetAsync(pden, 0, nh_bytes);
    cudaMemsetAsync(pacc, 0, nh_bytes);

    // fused node GEMM: Q2 | nodeK2 | nodeV2 = [kind,h] @ packed
    p = {pkR, ph, nullptr, FF, HH, 0, 0, 128, 0, 256, pBt + oN2,
         Q2b, nullptr, nullptr, pQ, NN, 384, 0,
         nullptr, nullptr, nullptr, nullptr, nullptr,
         pnK, pnV, K2b, V2b};
    launch_tg(p, false);
    // eK2
    p = {edge_h, nullptr, nullptr, FF, 0, 0, 0, 0, 0, 128, pBt + oKe2,
         nullptr, src, pnK, pex, EE, HH, 1,
         dst, pQ, pden, nullptr, nullptr,
         nullptr, nullptr, nullptr, nullptr};
    launch_tg(p, true);
    // eV2
    p = {edge_h, nullptr, nullptr, FF, 0, 0, 0, 0, 0, 128, pBt + oVe2,
         nullptr, src, pnV, nullptr, EE, HH, 2,
         dst, nullptr, nullptr, pacc, pex,
         nullptr, nullptr, nullptr, nullptr};
    launch_tg(p, true);

    node_div_k<<<(NN * HH / 4 + 255) / 256, 256>>>(pden, pacc, phn);

    // lin2 = concat(h_n1, h, kind) @ W2W + W2b (LN fused below)
    p = {phn, ph, pkR, HH, HH, FF, 0, HH, 2 * HH, 384, pBt + oW2,
         W2b, nullptr, nullptr, plin, NN, OUTD, 0,
         nullptr, nullptr, nullptr, nullptr, nullptr,
         nullptr, nullptr, nullptr, nullptr};
    launch_tg(p, false);

    // ===================== fused LN + gate + pool =====================
    cudaMemsetAsync(pSnum, 0, OUTD * sizeof(float));
    cudaMemsetAsync(pS, 0, sizeof(float));
    ln_gate_pool_k<<<LGP_BLOCKS, 256>>>(plin, ln2g, ln2b, gw, gb, pSnum, pS);
    pool_norm_k<<<3, 256>>>(pSnum, pS, out);
}

// round 17
// speedup vs baseline: 1.3278x; 1.1150x over previous
#include <cuda_runtime.h>
#include <math.h>
#include <stdint.h>

#define NN 50000
#define EE 500000
#define FF 128
#define HH 128
#define OUTD 768

// ---------------- scratch (device globals: no allocation allowed) ----------------
__device__ float g_Q  [(size_t)NN * HH];
__device__ float g_nK [(size_t)NN * HH];
__device__ float g_nV [(size_t)NN * HH];
__device__ float g_ex [(size_t)EE * HH];    // per-edge exp(Q[dst]*eK)
__device__ float g_kR [(size_t)NN * FF];    // kind, tf32-pre-rounded
__device__ float g_den[(size_t)NN * HH];
__device__ float g_acc[(size_t)NN * HH];
__device__ float g_hn [(size_t)NN * HH];    // tf32-pre-rounded at producer
__device__ float g_h  [(size_t)NN * HH];    // tf32-pre-rounded at producer
__device__ float g_lin[(size_t)NN * OUTD];
__device__ float g_Snum[OUTD];
__device__ float g_S[1];
__device__ float g_Bt[540672];   // packed transposed weights (tf32, k-permuted)

// ---------------- helpers ----------------
__device__ __forceinline__ uint32_t smem_u32(const void* p) {
    uint32_t a;
    asm("{ .reg .u64 t; cvta.to.shared.u64 t, %1; cvt.u32.u64 %0, t; }" : "=r"(a) : "l"(p));
    return a;
}
__device__ __forceinline__ uint32_t f2tf32(float x) {
    uint32_t u;
    asm("cvt.rna.tf32.f32 %0, %1;" : "=r"(u) : "f"(x));
    return u;
}
__device__ __forceinline__ float rnd(float x) { return __uint_as_float(f2tf32(x)); }
__device__ __forceinline__ void mma1688(float* c, const uint32_t* a,
                                        uint32_t b0, uint32_t b1) {
    asm volatile(
        "mma.sync.aligned.m16n8k8.row.col.f32.tf32.tf32.f32 "
        "{%0,%1,%2,%3}, {%4,%5,%6,%7}, {%8,%9}, {%0,%1,%2,%3};"
        : "+f"(c[0]), "+f"(c[1]), "+f"(c[2]), "+f"(c[3])
        : "r"(a[0]), "r"(a[1]), "r"(a[2]), "r"(a[3]), "r"(b0), "r"(b1));
}
__device__ __forceinline__ void cp16(uint32_t dst, const void* src, int szn) {
    asm volatile("cp.async.ca.shared.global [%0], [%1], 16, %2;"
                 :: "r"(dst), "l"(src), "r"(szn) : "memory");
}
__device__ __forceinline__ void cpa_commit() {
    asm volatile("cp.async.commit_group;" ::: "memory");
}
template <int N> __device__ __forceinline__ void cpa_wait() {
    asm volatile("cp.async.wait_group %0;" :: "n"(N) : "memory");
}
// vectorized fp32 reduction (sm_90+, PTX 8.1): one wavefront per 16B
__device__ __forceinline__ void red4(float* p, float a, float b, float c, float d) {
    asm volatile("red.global.add.v4.f32 [%0], {%1,%2,%3,%4};"
                 :: "l"(p), "f"(a), "f"(b), "f"(c), "f"(d) : "memory");
}

#define PADKA 20   // A smem stride (floats): conflict-free for scalar LDS
#define PADKB 24   // B smem stride (floats): conflict-free for LDS.64 (gID*12+tig)

// k-permutation within each 8-block (B ONLY): position 2t <- k=t, 2t+1 <- k=t+4
__device__ __forceinline__ int kperm(int k) {
    return (k & ~7) + ((k & 4) ? ((k & 3) * 2 + 1) : ((k & 3) * 2));
}

// ================= tf32 mma GEMM (512 thr, 32x32 warp tiles) ===================
// C = concat_k(A0,A1,A2) @ Bt^T. Bt [Ntot, ldb] K-major PRE-ROUNDED + k-PERMUTED.
// CVTA=1: A raw fp32 (cvt in-loop). CVTA=0: A pre-rounded tf32.
// mode 0: C = gemm + bias. If C1 set: blockIdx.x picks C/C1/C2 (+bias1/2), [M,128].
// mode 1: v = gemm + nK[src]; ex = exp(Q[dst]*v); C = ex; den[dst] += ex
// mode 2: v = gemm + nV[src]; acc[dst] += ex[row]*v (no C write)
struct TG {
    const float* A0; const float* A1; const float* A2;
    int k0, k1, k2;
    int bc0, bc1, bc2;
    int ldb;
    const float* Bt;
    const float* bias;
    const int* gidx; const float* gsrc;
    float* C; int M, Ntot;
    int mode;
    const int* dst; const float* Qm; float* den; float* acc; const float* ex;
    float* C1; float* C2; const float* bias1; const float* bias2;
};

#define A_ST 2560                     // 128*20 u32 per A stage
#define B_ST 3072                     // 128*24 u32 per B stage
#define GSMEM_BYTES ((3 * A_ST + 3 * B_ST) * 4)   // 67584; exchange needs 33792

template <int CVTA>
__global__ __launch_bounds__(512, 2) void mma_gemm(TG p) {
    extern __shared__ uint32_t sh[];
    const uint32_t sbase = smem_u32(sh);

    const int tid = threadIdx.x;
    const int lid = tid & 31, wid = tid >> 5;       // 16 warps
    const int warp_m = wid & 3, warp_n = wid >> 2;  // 4 x 4, 32x32 per warp
    const int gID = lid >> 2, tig = lid & 3;
    const int m0 = blockIdx.y * 128, n0 = blockIdx.x * 128;

    float c[2][4][4];
#pragma unroll
    for (int mt = 0; mt < 2; mt++)
#pragma unroll
        for (int nt = 0; nt < 4; nt++)
#pragma unroll
            for (int i = 0; i < 4; i++) c[mt][nt][i] = 0.f;

    const int K = p.k0 + p.k1 + p.k2;
    const int nch = K >> 4;

    auto load_chunk = [&](int kb) {
        int off = kb << 4;
        const float* A; int lda; int bc;
        if (off < p.k0)             { A = p.A0; lda = p.k0; bc = p.bc0; }
        else if (off < p.k0 + p.k1) { A = p.A1; lda = p.k1; bc = p.bc1; off -= p.k0; }
        else                        { A = p.A2; lda = p.k2; bc = p.bc2; off -= p.k0 + p.k1; }
        int st = kb % 3;
        uint32_t ab = sbase + st * (A_ST * 4);
        uint32_t bb = sbase + (3 * A_ST + st * B_ST) * 4;
        int row = tid >> 2, kq = tid & 3;
        int gm = m0 + row;
        int gmc = gm < p.M ? gm : p.M - 1;
        cp16(ab + row * 80 + kq * 16,
             A + (size_t)gmc * lda + off + kq * 4, gm < p.M ? 16 : 0);
        cp16(bb + row * 96 + kq * 16,
             p.Bt + (size_t)(n0 + row) * p.ldb + bc + off + kq * 4, 16);
        cpa_commit();
    };

    load_chunk(0);
    load_chunk(1);

    for (int kb = 0; kb < nch; kb++) {
        if (kb + 2 < nch) load_chunk(kb + 2);
        int np = nch - kb - 1; if (np > 2) np = 2;
        if (np == 2) cpa_wait<2>();
        else if (np == 1) cpa_wait<1>();
        else cpa_wait<0>();
        __syncthreads();

        int st = kb % 3;
        const uint32_t* shA = sh + st * A_ST;
        const uint32_t* shB = sh + 3 * A_ST + st * B_ST;
#pragma unroll
        for (int k8 = 0; k8 < 16; k8 += 8) {
            uint32_t a[2][4];
#pragma unroll
            for (int mt = 0; mt < 2; mt++) {
                int rb = (warp_m * 32 + mt * 16 + gID) * PADKA + k8 + tig;
                if (CVTA) {
                    a[mt][0] = f2tf32(__uint_as_float(shA[rb]));
                    a[mt][1] = f2tf32(__uint_as_float(shA[rb + 8 * PADKA]));
                    a[mt][2] = f2tf32(__uint_as_float(shA[rb + 4]));
                    a[mt][3] = f2tf32(__uint_as_float(shA[rb + 8 * PADKA + 4]));
                } else {
                    a[mt][0] = shA[rb];
                    a[mt][1] = shA[rb + 8 * PADKA];
                    a[mt][2] = shA[rb + 4];
                    a[mt][3] = shA[rb + 8 * PADKA + 4];
                }
            }
#pragma unroll
            for (int nt = 0; nt < 4; nt++) {
                // B permuted: positions (2tig, 2tig+1) = logical k (tig, tig+4)
                int nb = (warp_n * 32 + nt * 8 + gID) * PADKB + k8 + 2 * tig;
                uint2 b = *(const uint2*)&shB[nb];
#pragma unroll
                for (int mt = 0; mt < 2; mt++)
                    mma1688(c[mt][nt], a[mt], b.x, b.y);
            }
        }
        __syncthreads();
    }

    // ---- exchange epilogue: smem round-trip -> row-major coalesced handling ----
    float* exs = (float*)sh;
    float* Cb = p.C; const float* bb = p.bias; int stride = p.Ntot; int cb = n0;
    if (p.mode == 0 && p.C1) {
        Cb = (blockIdx.x == 0) ? p.C : (blockIdx.x == 1 ? p.C1 : p.C2);
        bb = (blockIdx.x == 0) ? p.bias : (blockIdx.x == 1 ? p.bias1 : p.bias2);
        stride = HH; cb = 0;
    }

#pragma unroll
    for (int h = 0; h < 2; h++) {
        __syncthreads();
        if ((warp_m >> 1) == h) {
            int rbase = (warp_m & 1) * 32;
#pragma unroll
            for (int mt = 0; mt < 2; mt++)
#pragma unroll
            for (int hf = 0; hf < 2; hf++) {
                int rl = rbase + mt * 16 + hf * 8 + gID;
#pragma unroll
                for (int nt = 0; nt < 4; nt++) {
                    int ad = rl * 132 + warp_n * 32 + nt * 8 + tig * 2;
                    *(float2*)&exs[ad] =
                        make_float2(c[mt][nt][hf * 2], c[mt][nt][hf * 2 + 1]);
                }
            }
        }
        __syncthreads();
#pragma unroll
        for (int r = 0; r < 4; r++) {
            int rl = wid * 4 + r;
            int gm = m0 + h * 64 + rl;
            if (gm >= p.M) break;
            float4 v = *(float4*)&exs[rl * 132 + lid * 4];
            if (p.mode == 0) {
                int col = cb + lid * 4;
                if (bb) {
                    float4 b4 = *(const float4*)(bb + col);
                    v.x += b4.x; v.y += b4.y; v.z += b4.z; v.w += b4.w;
                }
                *(float4*)(Cb + (size_t)gm * stride + col) = v;
            } else if (p.mode == 1) {
                int sn = p.gidx[gm], d = p.dst[gm];
                float4 k4 = *(const float4*)(p.gsrc + (size_t)sn * HH + lid * 4);
                float4 q4 = *(const float4*)(p.Qm + (size_t)d * HH + lid * 4);
                float e0 = expf(q4.x * (v.x + k4.x));
                float e1 = expf(q4.y * (v.y + k4.y));
                float e2 = expf(q4.z * (v.z + k4.z));
                float e3 = expf(q4.w * (v.w + k4.w));
                *(float4*)(p.C + (size_t)gm * HH + lid * 4) =
                    make_float4(e0, e1, e2, e3);
                red4(p.den + (size_t)d * HH + lid * 4, e0, e1, e2, e3);
            } else {
                int sn = p.gidx[gm], d = p.dst[gm];
                float4 g4 = *(const float4*)(p.gsrc + (size_t)sn * HH + lid * 4);
                float4 e4 = *(const float4*)(p.ex + (size_t)gm * HH + lid * 4);
                red4(p.acc + (size_t)d * HH + lid * 4,
                     e4.x * (v.x + g4.x), e4.y * (v.y + g4.y),
                     e4.z * (v.z + g4.z), e4.w * (v.w + g4.w));
            }
        }
    }
}

// ---------------- tf32 pre-round streaming copy (cheap GEMM-A sources) ---------
__global__ __launch_bounds__(256) void round_copy_k(
    const float* __restrict__ in, float* __restrict__ out, int n4)
{
    int i = blockIdx.x * 256 + threadIdx.x;
    if (i >= n4) return;
    float4 v = ((const float4*)in)[i];
    ((float4*)out)[i] = make_float4(rnd(v.x), rnd(v.y), rnd(v.z), rnd(v.w));
}

// ---------------- fused weight transposes (tf32 pre-round + k-permute) ---------
struct TransDesc { const float* W; float* O; int srcN; int KB; int ldb; };
struct TransParams { TransDesc t[14]; int start[15]; };

__global__ void transpose_all_k(TransParams tp) {
    __shared__ float t[32][33];
    int b = blockIdx.x;
    int i = 0;
#pragma unroll
    for (int j = 0; j < 14; j++)
        if (b >= tp.start[j + 1]) i = j + 1;
    const TransDesc d = tp.t[i];
    int rem = b - tp.start[i];
    int ntk = d.KB >> 5;
    int tx = (rem % ntk) * 32;       // k tile
    int ty = (rem / ntk) * 32;       // n tile
#pragma unroll
    for (int r = 0; r < 4; r++) {
        int k = tx + threadIdx.y + r * 8, n = ty + threadIdx.x;
        t[threadIdx.y + r * 8][threadIdx.x] = d.W[(size_t)k * d.srcN + n];
    }
    __syncthreads();
#pragma unroll
    for (int r = 0; r < 4; r++) {
        int n = ty + threadIdx.y + r * 8, k = tx + threadIdx.x;
        d.O[(size_t)n * d.ldb + kperm(k)] =
            __uint_as_float(f2tf32(t[threadIdx.x][threadIdx.y + r * 8]));
    }
}

// ---------------- node div (float4, tf32-rounded output: GEMM-A consumer) ------
__global__ __launch_bounds__(256) void node_div_k(
    const float* __restrict__ den, const float* __restrict__ acc,
    float* __restrict__ out)
{
    int i = (blockIdx.x * 256 + threadIdx.x) * 4;
    if (i < NN * HH) {
        float4 d4 = *(const float4*)(den + i);
        float4 a4 = *(const float4*)(acc + i);
        float4 o;
        o.x = rnd((d4.x > 0.f) ? a4.x / d4.x : 0.f);
        o.y = rnd((d4.y > 0.f) ? a4.y / d4.y : 0.f);
        o.z = rnd((d4.z > 0.f) ? a4.z / d4.z : 0.f);
        o.w = rnd((d4.w > 0.f) ? a4.w / d4.w : 0.f);
        *(float4*)(out + i) = o;
    }
}

// ---------------- layernorm 128 (tf32-rounded output: GEMM-A consumer) ---------
__global__ __launch_bounds__(128) void ln128_k(
    const float* __restrict__ x, const float* __restrict__ g,
    const float* __restrict__ b, float* __restrict__ y)
{
    int row = blockIdx.x, t = threadIdx.x;
    float v = x[(size_t)row * 128 + t];
    float s = v, s2 = v * v;
#pragma unroll
    for (int o = 16; o > 0; o >>= 1) {
        s  += __shfl_xor_sync(0xffffffffu, s, o);
        s2 += __shfl_xor_sync(0xffffffffu, s2, o);
    }
    __shared__ float ws[4], ws2[4];
    int w = t >> 5, l = t & 31;
    if (l == 0) { ws[w] = s; ws2[w] = s2; }
    __syncthreads();
    s  = ws[0] + ws[1] + ws[2] + ws[3];
    s2 = ws2[0] + ws2[1] + ws2[2] + ws2[3];
    float mu  = s * (1.f / 128.f);
    float var = s2 * (1.f / 128.f) - mu * mu;
    float r = rsqrtf(var + 1e-5f);
    float hv = (v - mu) * r * g[t] + b[t];
    y[(size_t)row * 128 + t] = rnd(hv);
}

// ---------------- fused LN768 + gate + pool ----------------
#define LGP_BLOCKS 400
__global__ __launch_bounds__(256) void ln_gate_pool_k(
    const float* __restrict__ lin, const float* __restrict__ g,
    const float* __restrict__ b, const float* __restrict__ gw,
    const float* __restrict__ gb, float* __restrict__ Snum,
    float* __restrict__ S)
{
    __shared__ float ps[8 * 768];
    int wid = threadIdx.x >> 5, lid = threadIdx.x & 31;
    int gwarp = blockIdx.x * 8 + wid;
    const int NW = LGP_BLOCKS * 8;

    float accv[24];
#pragma unroll
    for (int i = 0; i < 24; i++) accv[i] = 0.f;
    float eacc = 0.f;
    float gbv = gb[0];

    for (int row = gwarp; row < NN; row += NW) {
        const float* xr = lin + (size_t)row * 768;
        float x[24];
        float s = 0.f, s2 = 0.f;
#pragma unroll
        for (int k = 0; k < 6; k++) {
            float4 v = *(const float4*)(xr + k * 128 + lid * 4);
            x[k * 4 + 0] = v.x; x[k * 4 + 1] = v.y;
            x[k * 4 + 2] = v.z; x[k * 4 + 3] = v.w;
            s += v.x + v.y + v.z + v.w;
            s2 += v.x * v.x + v.y * v.y + v.z * v.z + v.w * v.w;
        }
#pragma unroll
        for (int o = 16; o > 0; o >>= 1) {
            s  += __shfl_xor_sync(0xffffffffu, s, o);
            s2 += __shfl_xor_sync(0xffffffffu, s2, o);
        }
        float mu  = s * (1.f / 768.f);
        float var = s2 * (1.f / 768.f) - mu * mu;
        float r = rsqrtf(var + 1e-5f);
        float dot = 0.f;
#pragma unroll
        for (int k = 0; k < 6; k++) {
            int col = k * 128 + lid * 4;
            float4 g4 = *(const float4*)(g + col);
            float4 b4 = *(const float4*)(b + col);
            float4 w4 = *(const float4*)(gw + col);
            float h0 = (x[k * 4 + 0] - mu) * r * g4.x + b4.x;
            float h1 = (x[k * 4 + 1] - mu) * r * g4.y + b4.y;
            float h2 = (x[k * 4 + 2] - mu) * r * g4.z + b4.z;
            float h3 = (x[k * 4 + 3] - mu) * r * g4.w + b4.w;
            x[k * 4 + 0] = h0; x[k * 4 + 1] = h1;
            x[k * 4 + 2] = h2; x[k * 4 + 3] = h3;
            dot = fmaf(h0, w4.x, dot); dot = fmaf(h1, w4.y, dot);
            dot = fmaf(h2, w4.z, dot); dot = fmaf(h3, w4.w, dot);
        }
#pragma unroll
        for (int o = 16; o > 0; o >>= 1)
            dot += __shfl_xor_sync(0xffffffffu, dot, o);
        float e = expf(dot + gbv);
        eacc += e;
#pragma unroll
        for (int i = 0; i < 24; i++) accv[i] = fmaf(e, x[i], accv[i]);
    }

#pragma unroll
    for (int k = 0; k < 6; k++) {
        int col = k * 128 + lid * 4;
        *(float4*)&ps[wid * 768 + col] = make_float4(
            accv[k * 4 + 0], accv[k * 4 + 1], accv[k * 4 + 2], accv[k * 4 + 3]);
    }
    __syncthreads();
    for (int cidx = threadIdx.x; cidx < 768; cidx += 256) {
        float sum = 0.f;
#pragma unroll
        for (int w = 0; w < 8; w++) sum += ps[w * 768 + cidx];
        atomicAdd(Snum + cidx, sum);
    }
    if (lid == 0) atomicAdd(S, eacc);
}

__global__ void pool_norm_k(const float* __restrict__ Snum,
                            const float* __restrict__ S,
                            float* __restrict__ out) {
    int c = blockIdx.x * 256 + threadIdx.x;
    if (c < OUTD) out[c] = Snum[c] / S[0];
}

// ---------------- host ----------------
static void launch_tg(const TG& p, bool cvtA) {
    dim3 grid(p.Ntot / 128, (p.M + 127) / 128);
    if (cvtA) mma_gemm<1><<<grid, 512, GSMEM_BYTES>>>(p);
    else      mma_gemm<0><<<grid, 512, GSMEM_BYTES>>>(p);
}

extern "C" void kernel_launch(void* const* d_in, const int* in_sizes, int n_in,
                              void* d_out, int out_size) {
    const float* kind   = (const float*)d_in[0];
    const float* edge_h = (const float*)d_in[1];
    const int*   src    = (const int*)  d_in[2];
    const int*   dst    = (const int*)  d_in[3];
    const float* KW  = (const float*)d_in[4];  const float* Kb  = (const float*)d_in[5];
    const float* VW  = (const float*)d_in[6];  const float* Vb  = (const float*)d_in[7];
    const float* QW  = (const float*)d_in[8];  const float* Qb  = (const float*)d_in[9];
    const float* WW  = (const float*)d_in[10]; const float* Wb  = (const float*)d_in[11];
    const float* K2W = (const float*)d_in[12]; const float* K2b = (const float*)d_in[13];
    const float* V2W = (const float*)d_in[14]; const float* V2b = (const float*)d_in[15];
    const float* Q2W = (const float*)d_in[16]; const float* Q2b = (const float*)d_in[17];
    const float* W2W = (const float*)d_in[18]; const float* W2b = (const float*)d_in[19];
    const float* ln1g = (const float*)d_in[20]; const float* ln1b = (const float*)d_in[21];
    const float* ln2g = (const float*)d_in[22]; const float* ln2b = (const float*)d_in[23];
    const float* gw  = (const float*)d_in[24]; const float* gb  = (const float*)d_in[25];
    float* out = (float*)d_out;

    static float *pQ = nullptr, *pnK, *pnV, *pex, *pkR, *pden, *pacc,
                 *phn, *ph, *plin, *pSnum, *pS, *pBt;
    if (!pQ) {
        cudaGetSymbolAddress((void**)&pQ,   g_Q);
        cudaGetSymbolAddress((void**)&pnK,  g_nK);
        cudaGetSymbolAddress((void**)&pnV,  g_nV);
        cudaGetSymbolAddress((void**)&pex,  g_ex);
        cudaGetSymbolAddress((void**)&pkR,  g_kR);
        cudaGetSymbolAddress((void**)&pden, g_den);
        cudaGetSymbolAddress((void**)&pacc, g_acc);
        cudaGetSymbolAddress((void**)&phn,  g_hn);
        cudaGetSymbolAddress((void**)&ph,   g_h);
        cudaGetSymbolAddress((void**)&plin, g_lin);
        cudaGetSymbolAddress((void**)&pSnum, g_Snum);
        cudaGetSymbolAddress((void**)&pS,   g_S);
        cudaGetSymbolAddress((void**)&pBt,  g_Bt);
        cudaFuncSetAttribute(mma_gemm<0>, cudaFuncAttributeMaxDynamicSharedMemorySize,
                             GSMEM_BYTES);
        cudaFuncSetAttribute(mma_gemm<1>, cudaFuncAttributeMaxDynamicSharedMemorySize,
                             GSMEM_BYTES);
    }

    // packed transposed-weight offsets (floats)
    const int oN1  = 0;        // [384,128]: Q | nodeK | nodeV
    const int oKe1 = 49152;    // [128,128]: KW edge part
    const int oVe1 = 65536;    // [128,128]: VW edge part
    const int oW1  = 81920;    // [128,256]: WW full
    const int oN2  = 114688;   // [384,256]: Q2 | K2 node | V2 node
    const int oKe2 = 212992;   // [128,128]: K2W edge part
    const int oVe2 = 229376;   // [128,128]: V2W edge part
    const int oW2  = 245760;   // [768,384]: W2W full

    TransParams tp;
    tp.t[0]  = {QW,                pBt + oN1,             128, 128, 128};
    tp.t[1]  = {KW,                pBt + oN1 + 128 * 128, 128, 128, 128};
    tp.t[2]  = {VW,                pBt + oN1 + 256 * 128, 128, 128, 128};
    tp.t[3]  = {KW + 128 * 128,    pBt + oKe1,            128, 128, 128};
    tp.t[4]  = {VW + 128 * 128,    pBt + oVe1,            128, 128, 128};
    tp.t[5]  = {WW,                pBt + oW1,             128, 256, 256};
    tp.t[6]  = {Q2W,               pBt + oN2,             128, 256, 256};
    tp.t[7]  = {K2W,               pBt + oN2 + 128 * 256,       128, 128, 256};
    tp.t[8]  = {K2W + 256 * 128,   pBt + oN2 + 128 * 256 + 128, 128, 128, 256};
    tp.t[9]  = {V2W,               pBt + oN2 + 256 * 256,       128, 128, 256};
    tp.t[10] = {V2W + 256 * 128,   pBt + oN2 + 256 * 256 + 128, 128, 128, 256};
    tp.t[11] = {K2W + 128 * 128,   pBt + oKe2,            128, 128, 128};
    tp.t[12] = {V2W + 128 * 128,   pBt + oVe2,            128, 128, 128};
    tp.t[13] = {W2W,               pBt + oW2,             768, 384, 384};
    int s = 0;
    for (int i = 0; i < 14; i++) {
        tp.start[i] = s;
        s += (tp.t[i].srcN >> 5) * (tp.t[i].KB >> 5);
    }
    tp.start[14] = s;
    transpose_all_k<<<s, dim3(32, 8)>>>(tp);

    // pre-round kind only (cheap, reused in 4 GEMMs); edge_h stays raw (CVTA=1)
    round_copy_k<<<(NN * FF / 4 + 255) / 256, 256>>>(kind, pkR, NN * FF / 4);

    const size_t nh_bytes = (size_t)NN * HH * sizeof(float);
    TG p;

    // ===================== layer 1 =====================
    cudaMemsetAsync(pden, 0, nh_bytes);
    cudaMemsetAsync(pacc, 0, nh_bytes);

    // fused node GEMM: Q | nodeK | nodeV = kind @ {QW, KW[0:F], VW[0:F]}
    p = {pkR, nullptr, nullptr, FF, 0, 0, 0, 0, 0, 128, pBt + oN1,
         Qb, nullptr, nullptr, pQ, NN, 384, 0,
         nullptr, nullptr, nullptr, nullptr, nullptr,
         pnK, pnV, Kb, Vb};
    launch_tg(p, false);
    // eK fused: ex = exp(Q[dst] * (edge_h@KWe + nodeK[src])); den[dst]+=ex
    p = {edge_h, nullptr, nullptr, FF, 0, 0, 0, 0, 0, 128, pBt + oKe1,
         nullptr, src, pnK, pex, EE, HH, 1,
         dst, pQ, pden, nullptr, nullptr,
         nullptr, nullptr, nullptr, nullptr};
    launch_tg(p, true);
    // eV fused: acc[dst] += ex * (edge_h@VWe + nodeV[src])
    p = {edge_h, nullptr, nullptr, FF, 0, 0, 0, 0, 0, 128, pBt + oVe1,
         nullptr, src, pnV, nullptr, EE, HH, 2,
         dst, nullptr, nullptr, pacc, pex,
         nullptr, nullptr, nullptr, nullptr};
    launch_tg(p, true);

    node_div_k<<<(NN * HH / 4 + 255) / 256, 256>>>(pden, pacc, phn);

    // lin1 = concat(h_n, kind) @ WW + Wb ; h = LN(lin1)
    p = {phn, pkR, nullptr, HH, FF, 0, 0, HH, 0, 256, pBt + oW1,
         Wb, nullptr, nullptr, plin, NN, HH, 0,
         nullptr, nullptr, nullptr, nullptr, nullptr,
         nullptr, nullptr, nullptr, nullptr};
    launch_tg(p, false);
    ln128_k<<<NN, 128>>>(plin, ln1g, ln1b, ph);

    // ===================== layer 2 =====================
    cudaMemsetAsync(pden, 0, nh_bytes);
    cudaMemsetAsync(pacc, 0, nh_bytes);

    // fused node GEMM: Q2 | nodeK2 | nodeV2 = [kind,h] @ packed
    p = {pkR, ph, nullptr, FF, HH, 0, 0, 128, 0, 256, pBt + oN2,
         Q2b, nullptr, nullptr, pQ, NN, 384, 0,
         nullptr, nullptr, nullptr, nullptr, nullptr,
         pnK, pnV, K2b, V2b};
    launch_tg(p, false);
    // eK2
    p = {edge_h, nullptr, nullptr, FF, 0, 0, 0, 0, 0, 128, pBt + oKe2,
         nullptr, src, pnK, pex, EE, HH, 1,
         dst, pQ, pden, nullptr, nullptr,
         nullptr, nullptr, nullptr, nullptr};
    launch_tg(p, true);
    // eV2
    p = {edge_h, nullptr, nullptr, FF, 0, 0, 0, 0, 0, 128, pBt + oVe2,
         nullptr, src, pnV, nullptr, EE, HH, 2,
         dst, nullptr, nullptr, pacc, pex,
         nullptr, nullptr, nullptr, nullptr};
    launch_tg(p, true);

    node_div_k<<<(NN * HH / 4 + 255) / 256, 256>>>(pden, pacc, phn);

    // lin2 = concat(h_n1, h, kind) @ W2W + W2b (LN fused below)
    p = {phn, ph, pkR, HH, HH, FF, 0, HH, 2 * HH, 384, pBt + oW2,
         W2b, nullptr, nullptr, plin, NN, OUTD, 0,
         nullptr, nullptr, nullptr, nullptr, nullptr,
         nullptr, nullptr, nullptr, nullptr};
    launch_tg(p, false);

    // ===================== fused LN + gate + pool =====================
    cudaMemsetAsync(pSnum, 0, OUTD * sizeof(float));
    cudaMemsetAsync(pS, 0, sizeof(float));
    ln_gate_pool_k<<<LGP_BLOCKS, 256>>>(plin, ln2g, ln2b, gw, gb, pSnum, pS);
    pool_norm_k<<<3, 256>>>(pSnum, pS, out);
}